// round 1
// baseline (speedup 1.0000x reference)
#include <cuda_runtime.h>

// Talking-heads attention, fp32 baseline.
// B=16, N=576, C=768, H=12, HD=64.
//
// Pipeline (5 kernels, all graph-capturable, no allocs):
//  1) qkv_kernel:     qkv = x @ Wqkv^T, scattered to q/k/v in (B,H,N,HD); q pre-scaled.
//  2) score_kernel:   mixed[g,m,n] = sum_h Wl[g,h]*(q_h[m]·k_h[n]) + bl[g]  (pre-mix fused)
//  3) softmax_mix:    rowwise softmax over n per head, then post-mix with Ww + bw (fused)
//  4) av_kernel:      o1[b,m,h*64+d] = sum_n attn2[b,h,m,n] * v[b,h,n,d]
//  5) proj_kernel:    out = o1 @ Wproj^T + bproj

#define BB 16
#define NN 576
#define CC 768
#define HH 12
#define HDIM 64
#define MTOT (BB * NN)     // 9216
#define SCALE 0.125f       // 64^-0.5

// ---- scratch (device globals; allocation-free) ----
__device__ float g_q[BB * HH * NN * HDIM];      // 27 MB
__device__ float g_k[BB * HH * NN * HDIM];      // 27 MB
__device__ float g_v[BB * HH * NN * HDIM];      // 27 MB
__device__ float g_attn[BB * HH * NN * NN];     // 255 MB (mixed scores, then mixed probs)
__device__ float g_o1[BB * NN * CC];            // 28 MB (pre-projection attention output)

// ============================================================================
// Kernel 1: QKV projection. C[m,j] = sum_k x[m,k]*Wqkv[j,k]; scatter to q/k/v.
// 128x128x16 tiles, 256 threads, 8x8 per thread.
// Grid: (2304/128=18, 9216/128=72)
// ============================================================================
__global__ __launch_bounds__(256) void qkv_kernel(const float* __restrict__ x,
                                                  const float* __restrict__ W) {
    __shared__ float As[16][128];
    __shared__ float Bs[16][128];
    const int m0 = blockIdx.y * 128;
    const int j0 = blockIdx.x * 128;
    const int tid = threadIdx.x;
    const int tx = tid & 15, ty = tid >> 4;
    const int lr = tid >> 2;            // 0..63
    const int lc = (tid & 3) << 2;      // 0,4,8,12

    float acc[8][8];
#pragma unroll
    for (int i = 0; i < 8; i++)
#pragma unroll
        for (int j = 0; j < 8; j++) acc[i][j] = 0.f;

    for (int k0 = 0; k0 < CC; k0 += 16) {
        float4 a0 = *(const float4*)&x[(size_t)(m0 + lr) * CC + k0 + lc];
        float4 a1 = *(const float4*)&x[(size_t)(m0 + lr + 64) * CC + k0 + lc];
        float4 b0 = *(const float4*)&W[(size_t)(j0 + lr) * CC + k0 + lc];
        float4 b1 = *(const float4*)&W[(size_t)(j0 + lr + 64) * CC + k0 + lc];
        __syncthreads();
        As[lc + 0][lr] = a0.x; As[lc + 1][lr] = a0.y; As[lc + 2][lr] = a0.z; As[lc + 3][lr] = a0.w;
        As[lc + 0][lr + 64] = a1.x; As[lc + 1][lr + 64] = a1.y; As[lc + 2][lr + 64] = a1.z; As[lc + 3][lr + 64] = a1.w;
        Bs[lc + 0][lr] = b0.x; Bs[lc + 1][lr] = b0.y; Bs[lc + 2][lr] = b0.z; Bs[lc + 3][lr] = b0.w;
        Bs[lc + 0][lr + 64] = b1.x; Bs[lc + 1][lr + 64] = b1.y; Bs[lc + 2][lr + 64] = b1.z; Bs[lc + 3][lr + 64] = b1.w;
        __syncthreads();
#pragma unroll
        for (int kk = 0; kk < 16; kk++) {
            float4 ra0 = *(const float4*)&As[kk][ty * 8];
            float4 ra1 = *(const float4*)&As[kk][ty * 8 + 4];
            float4 rb0 = *(const float4*)&Bs[kk][tx * 8];
            float4 rb1 = *(const float4*)&Bs[kk][tx * 8 + 4];
            float ra[8] = {ra0.x, ra0.y, ra0.z, ra0.w, ra1.x, ra1.y, ra1.z, ra1.w};
            float rb[8] = {rb0.x, rb0.y, rb0.z, rb0.w, rb1.x, rb1.y, rb1.z, rb1.w};
#pragma unroll
            for (int i = 0; i < 8; i++)
#pragma unroll
                for (int j = 0; j < 8; j++) acc[i][j] += ra[i] * rb[j];
        }
    }

    // Scatter: j = t*768 + h*64 + d ; m = b*576 + n
#pragma unroll
    for (int i = 0; i < 8; i++) {
        int m = m0 + ty * 8 + i;
        int b = m / NN, n = m % NN;
#pragma unroll
        for (int j = 0; j < 8; j++) {
            int jj = j0 + tx * 8 + j;
            int t = jj / CC;
            int r = jj - t * CC;
            int h = r >> 6;
            int d = r & 63;
            int idx = ((b * HH + h) * NN + n) * HDIM + d;
            float v = acc[i][j];
            if (t == 0)      g_q[idx] = v * SCALE;
            else if (t == 1) g_k[idx] = v;
            else             g_v[idx] = v;
        }
    }
}

// ============================================================================
// Kernel 2: scores + pre-softmax talking-heads mix (fused, mix in registers).
// Block = (b, 32 m-rows, 32 n-cols). Per head: load q/k tiles, each thread
// computes 2x2 raw scores, immediately folds them into 12 mixed accumulators.
// Grid: (18 nt, 18 mt, 16 b), 256 threads.
// ============================================================================
__global__ __launch_bounds__(256) void score_kernel(const float* __restrict__ Wl,
                                                    const float* __restrict__ bl) {
    __shared__ float qs[32][68];   // +4 pad: 2-way max conflict on k reads
    __shared__ float ks[32][68];
    __shared__ float wls[HH * HH];
    __shared__ float bls[HH];

    const int b = blockIdx.z;
    const int m0 = blockIdx.y * 32;
    const int n0 = blockIdx.x * 32;
    const int tid = threadIdx.x;
    const int tx = tid & 15, ty = tid >> 4;
    const int r = tid >> 3;            // 0..31
    const int c = (tid & 7) * 8;       // 0..56

    if (tid < HH * HH) wls[tid] = Wl[tid];
    if (tid < HH) bls[tid] = bl[tid];

    float acc[HH][4];
#pragma unroll
    for (int g = 0; g < HH; g++)
#pragma unroll
        for (int p = 0; p < 4; p++) acc[g][p] = 0.f;

    for (int h = 0; h < HH; h++) {
        const float* qp = &g_q[((size_t)((b * HH + h) * NN + m0 + r)) * HDIM + c];
        const float* kp = &g_k[((size_t)((b * HH + h) * NN + n0 + r)) * HDIM + c];
        float4 q0 = *(const float4*)qp;
        float4 q1 = *(const float4*)(qp + 4);
        float4 k0 = *(const float4*)kp;
        float4 k1 = *(const float4*)(kp + 4);
        __syncthreads();
        *(float4*)&qs[r][c] = q0;
        *(float4*)&qs[r][c + 4] = q1;
        *(float4*)&ks[r][c] = k0;
        *(float4*)&ks[r][c + 4] = k1;
        __syncthreads();

        float s0 = 0.f, s1 = 0.f, s2 = 0.f, s3 = 0.f;
#pragma unroll
        for (int d = 0; d < HDIM; d += 4) {
            float4 a0 = *(const float4*)&qs[ty * 2][d];
            float4 a1 = *(const float4*)&qs[ty * 2 + 1][d];
            float4 b0 = *(const float4*)&ks[tx][d];
            float4 b1 = *(const float4*)&ks[tx + 16][d];
            s0 += a0.x * b0.x + a0.y * b0.y + a0.z * b0.z + a0.w * b0.w;
            s1 += a0.x * b1.x + a0.y * b1.y + a0.z * b1.z + a0.w * b1.w;
            s2 += a1.x * b0.x + a1.y * b0.y + a1.z * b0.z + a1.w * b0.w;
            s3 += a1.x * b1.x + a1.y * b1.y + a1.z * b1.z + a1.w * b1.w;
        }
        // fold into mixed accumulators: mixed[g] += Wl[g,h] * s
#pragma unroll
        for (int g = 0; g < HH; g++) {
            float wl = wls[g * HH + h];
            acc[g][0] += wl * s0;
            acc[g][1] += wl * s1;
            acc[g][2] += wl * s2;
            acc[g][3] += wl * s3;
        }
    }

#pragma unroll
    for (int g = 0; g < HH; g++) {
        float bg = bls[g];
#pragma unroll
        for (int p = 0; p < 4; p++) {
            int m = m0 + ty * 2 + (p >> 1);
            int n = n0 + tx + 16 * (p & 1);
            g_attn[(size_t)((b * HH + g) * NN + m) * NN + n] = acc[g][p] + bg;
        }
    }
}

// ============================================================================
// Kernel 3: rowwise softmax (per head) + post-softmax talking-heads mix.
// Block per (b, m). 384 threads = 12 warps, warp w owns head w (warp-local
// max/sum reductions, no block reduction). Then block-wide mix over heads.
// ============================================================================
__global__ __launch_bounds__(384) void softmax_mix_kernel(const float* __restrict__ Ww,
                                                          const float* __restrict__ bw) {
    __shared__ float sm[HH][NN];     // 27648 B
    __shared__ float wws[HH * HH];
    __shared__ float bws[HH];

    const int bm = blockIdx.x;
    const int b = bm / NN, m = bm % NN;
    const int tid = threadIdx.x;
    const int lane = tid & 31;
    const int wid = tid >> 5;        // 0..11 = head

    if (tid < HH * HH) wws[tid] = Ww[tid];
    if (tid < HH) bws[tid] = bw[tid];

    // cooperative load of all 12 head-rows
    for (int idx = tid; idx < HH * NN; idx += 384) {
        int h = idx / NN, n = idx - h * NN;
        sm[h][n] = g_attn[(size_t)((b * HH + h) * NN + m) * NN + n];
    }
    __syncthreads();

    // warp w: softmax of head w over n
    {
        const int h = wid;
        float mx = -1e30f;
        for (int n = lane; n < NN; n += 32) mx = fmaxf(mx, sm[h][n]);
#pragma unroll
        for (int o = 16; o > 0; o >>= 1) mx = fmaxf(mx, __shfl_xor_sync(0xffffffffu, mx, o));
        float sum = 0.f;
        for (int n = lane; n < NN; n += 32) {
            float e = __expf(sm[h][n] - mx);
            sm[h][n] = e;
            sum += e;
        }
#pragma unroll
        for (int o = 16; o > 0; o >>= 1) sum += __shfl_xor_sync(0xffffffffu, sum, o);
        float inv = 1.f / sum;
        for (int n = lane; n < NN; n += 32) sm[h][n] *= inv;
    }
    __syncthreads();

    // post-mix: attn2[g,n] = bw[g] + sum_h Ww[g,h]*P[h,n]
    for (int n = tid; n < NN; n += 384) {
        float p[HH];
#pragma unroll
        for (int h = 0; h < HH; h++) p[h] = sm[h][n];
#pragma unroll
        for (int g = 0; g < HH; g++) {
            float o = bws[g];
#pragma unroll
            for (int h = 0; h < HH; h++) o += wws[g * HH + h] * p[h];
            g_attn[(size_t)((b * HH + g) * NN + m) * NN + n] = o;
        }
    }
}

// ============================================================================
// Kernel 4: O = attn2 @ V per (b,h). (576x576)@(576x64).
// Block = 64 m-rows x 64 d (full head dim), BK=64, 256 threads, 4x4/thread.
// Grid: (9, 12, 16)
// ============================================================================
__global__ __launch_bounds__(256) void av_kernel() {
    __shared__ float As[64][65];   // As[n][m] (transposed), pad
    __shared__ float Vs[64][64];   // Vs[n][d]

    const int b = blockIdx.z, h = blockIdx.y;
    const int m0 = blockIdx.x * 64;
    const int tid = threadIdx.x;
    const int tx = tid & 15, ty = tid >> 4;
    const int r = tid >> 2, fc = tid & 3;

    const float* Ab = &g_attn[(size_t)((b * HH + h) * NN + m0) * NN];
    const float* Vb = &g_v[(size_t)((b * HH + h) * NN) * HDIM];

    float acc[4][4];
#pragma unroll
    for (int i = 0; i < 4; i++)
#pragma unroll
        for (int j = 0; j < 4; j++) acc[i][j] = 0.f;

    for (int n0 = 0; n0 < NN; n0 += 64) {
        float4 av[4], vv[4];
#pragma unroll
        for (int k = 0; k < 4; k++) {
            int f = fc + 4 * k;
            av[k] = *(const float4*)&Ab[(size_t)r * NN + n0 + f * 4];
            vv[k] = *(const float4*)&Vb[(size_t)(n0 + r) * HDIM + f * 4];
        }
        __syncthreads();
#pragma unroll
        for (int k = 0; k < 4; k++) {
            int f = fc + 4 * k;
            As[f * 4 + 0][r] = av[k].x;
            As[f * 4 + 1][r] = av[k].y;
            As[f * 4 + 2][r] = av[k].z;
            As[f * 4 + 3][r] = av[k].w;
            *(float4*)&Vs[r][f * 4] = vv[k];
        }
        __syncthreads();
#pragma unroll
        for (int kk = 0; kk < 64; kk++) {
            float a[4], v[4];
#pragma unroll
            for (int i = 0; i < 4; i++) a[i] = As[kk][ty + 16 * i];
#pragma unroll
            for (int j = 0; j < 4; j++) v[j] = Vs[kk][tx + 16 * j];
#pragma unroll
            for (int i = 0; i < 4; i++)
#pragma unroll
                for (int j = 0; j < 4; j++) acc[i][j] += a[i] * v[j];
        }
    }

#pragma unroll
    for (int i = 0; i < 4; i++) {
        int m = m0 + ty + 16 * i;
#pragma unroll
        for (int j = 0; j < 4; j++) {
            g_o1[(size_t)(b * NN + m) * CC + h * HDIM + tx + 16 * j] = acc[i][j];
        }
    }
}

// ============================================================================
// Kernel 5: out = o1 @ Wproj^T + bproj. Same scheme as kernel 1.
// Grid: (768/128=6, 72)
// ============================================================================
__global__ __launch_bounds__(256) void proj_kernel(const float* __restrict__ W,
                                                   const float* __restrict__ bias,
                                                   float* __restrict__ out) {
    __shared__ float As[16][128];
    __shared__ float Bs[16][128];
    const int m0 = blockIdx.y * 128;
    const int j0 = blockIdx.x * 128;
    const int tid = threadIdx.x;
    const int tx = tid & 15, ty = tid >> 4;
    const int lr = tid >> 2;
    const int lc = (tid & 3) << 2;

    float acc[8][8];
#pragma unroll
    for (int i = 0; i < 8; i++)
#pragma unroll
        for (int j = 0; j < 8; j++) acc[i][j] = 0.f;

    for (int k0 = 0; k0 < CC; k0 += 16) {
        float4 a0 = *(const float4*)&g_o1[(size_t)(m0 + lr) * CC + k0 + lc];
        float4 a1 = *(const float4*)&g_o1[(size_t)(m0 + lr + 64) * CC + k0 + lc];
        float4 b0 = *(const float4*)&W[(size_t)(j0 + lr) * CC + k0 + lc];
        float4 b1 = *(const float4*)&W[(size_t)(j0 + lr + 64) * CC + k0 + lc];
        __syncthreads();
        As[lc + 0][lr] = a0.x; As[lc + 1][lr] = a0.y; As[lc + 2][lr] = a0.z; As[lc + 3][lr] = a0.w;
        As[lc + 0][lr + 64] = a1.x; As[lc + 1][lr + 64] = a1.y; As[lc + 2][lr + 64] = a1.z; As[lc + 3][lr + 64] = a1.w;
        Bs[lc + 0][lr] = b0.x; Bs[lc + 1][lr] = b0.y; Bs[lc + 2][lr] = b0.z; Bs[lc + 3][lr] = b0.w;
        Bs[lc + 0][lr + 64] = b1.x; Bs[lc + 1][lr + 64] = b1.y; Bs[lc + 2][lr + 64] = b1.z; Bs[lc + 3][lr + 64] = b1.w;
        __syncthreads();
#pragma unroll
        for (int kk = 0; kk < 16; kk++) {
            float4 ra0 = *(const float4*)&As[kk][ty * 8];
            float4 ra1 = *(const float4*)&As[kk][ty * 8 + 4];
            float4 rb0 = *(const float4*)&Bs[kk][tx * 8];
            float4 rb1 = *(const float4*)&Bs[kk][tx * 8 + 4];
            float ra[8] = {ra0.x, ra0.y, ra0.z, ra0.w, ra1.x, ra1.y, ra1.z, ra1.w};
            float rb[8] = {rb0.x, rb0.y, rb0.z, rb0.w, rb1.x, rb1.y, rb1.z, rb1.w};
#pragma unroll
            for (int i = 0; i < 8; i++)
#pragma unroll
                for (int j = 0; j < 8; j++) acc[i][j] += ra[i] * rb[j];
        }
    }

#pragma unroll
    for (int i = 0; i < 8; i++) {
        int m = m0 + ty * 8 + i;
#pragma unroll
        for (int j = 0; j < 8; j++) {
            int jj = j0 + tx * 8 + j;
            out[(size_t)m * CC + jj] = acc[i][j] + __ldg(&bias[jj]);
        }
    }
}

// ============================================================================
extern "C" void kernel_launch(void* const* d_in, const int* in_sizes, int n_in,
                              void* d_out, int out_size) {
    const float* x     = (const float*)d_in[0];
    const float* Wqkv  = (const float*)d_in[1];
    const float* Wl    = (const float*)d_in[2];
    const float* bl    = (const float*)d_in[3];
    const float* Ww    = (const float*)d_in[4];
    const float* bw    = (const float*)d_in[5];
    const float* Wproj = (const float*)d_in[6];
    const float* bproj = (const float*)d_in[7];
    float* out = (float*)d_out;

    qkv_kernel<<<dim3(18, 72), 256>>>(x, Wqkv);
    score_kernel<<<dim3(18, 18, 16), 256>>>(Wl, bl);
    softmax_mix_kernel<<<MTOT, 384>>>(Ww, bw);
    av_kernel<<<dim3(9, 12, 16), 256>>>();
    proj_kernel<<<dim3(6, 72), 256>>>(Wproj, bproj, out);
}

// round 2
// speedup vs baseline: 1.1128x; 1.1128x over previous
#include <cuda_runtime.h>

// Talking-heads attention, fp32 + packed f32x2 FMA.
// B=16, N=576, C=768, H=12, HD=64.
//
// Pipeline:
//  1) qkv_kernel:     qkv = x @ Wqkv^T -> q/k/v (B,H,N,HD); q pre-scaled.
//  2) score_kernel:   raw[b,h,m,n] = q_h[m] . k_h[n]          (pure batched GEMM)
//  3) softmax_mix:    pre-mix (Wl,bl) -> softmax -> post-mix (Ww,bw)   (fused)
//  4) av_kernel:      o1 = attn2 @ v
//  5) proj_kernel:    out = o1 @ Wproj^T + bproj

#define BB 16
#define NN 576
#define CC 768
#define HH 12
#define HDIM 64
#define MTOT (BB * NN)
#define SCALE 0.125f

typedef unsigned long long u64;

// ---- packed f32x2 helpers (FFMA2: full-rate fp32, identical numerics) ----
__device__ __forceinline__ u64 splat2(float x) {
    u64 r; asm("mov.b64 %0, {%1,%1};" : "=l"(r) : "f"(x)); return r;
}
__device__ __forceinline__ void fma2(u64& d, u64 a, u64 b) {
    asm("fma.rn.f32x2 %0, %1, %2, %0;" : "+l"(d) : "l"(a), "l"(b));
}
__device__ __forceinline__ float2 unpack2(u64 v) {
    float lo, hi; asm("mov.b64 {%0,%1}, %2;" : "=f"(lo), "=f"(hi) : "l"(v));
    return make_float2(lo, hi);
}

// ---- scratch ----
__device__ float g_q[BB * HH * NN * HDIM];
__device__ float g_k[BB * HH * NN * HDIM];
__device__ float g_v[BB * HH * NN * HDIM];
__device__ float g_attn[BB * HH * NN * NN];   // raw scores, then mixed probs
__device__ float g_o1[BB * NN * CC];

// ============================================================================
// Kernel 1: QKV projection. 128x128x16 tiles, 256 thr, 8x8/thread (f32x2),
// split-half column mapping (conflict-free LDS.64), global->reg prefetch.
// Grid: (18, 72)
// ============================================================================
__global__ __launch_bounds__(256) void qkv_kernel(const float* __restrict__ x,
                                                  const float* __restrict__ W) {
    __shared__ float As[16][128];
    __shared__ float Bs[16][128];
    const int m0 = blockIdx.y * 128;
    const int j0 = blockIdx.x * 128;
    const int tid = threadIdx.x;
    const int tx = tid & 15, ty = tid >> 4;
    const int lr = tid >> 2;
    const int lc = (tid & 3) << 2;

    u64 acc[8][4];
#pragma unroll
    for (int i = 0; i < 8; i++)
#pragma unroll
        for (int j = 0; j < 4; j++) acc[i][j] = 0ull;

    const float* xa = &x[(size_t)(m0 + lr) * CC + lc];
    const float* wb = &W[(size_t)(j0 + lr) * CC + lc];

    float4 a0 = *(const float4*)xa;
    float4 a1 = *(const float4*)(xa + (size_t)64 * CC);
    float4 b0 = *(const float4*)wb;
    float4 b1 = *(const float4*)(wb + (size_t)64 * CC);

    for (int k0 = 0; k0 < CC; k0 += 16) {
        __syncthreads();
        As[lc + 0][lr] = a0.x; As[lc + 1][lr] = a0.y; As[lc + 2][lr] = a0.z; As[lc + 3][lr] = a0.w;
        As[lc + 0][lr + 64] = a1.x; As[lc + 1][lr + 64] = a1.y; As[lc + 2][lr + 64] = a1.z; As[lc + 3][lr + 64] = a1.w;
        Bs[lc + 0][lr] = b0.x; Bs[lc + 1][lr] = b0.y; Bs[lc + 2][lr] = b0.z; Bs[lc + 3][lr] = b0.w;
        Bs[lc + 0][lr + 64] = b1.x; Bs[lc + 1][lr + 64] = b1.y; Bs[lc + 2][lr + 64] = b1.z; Bs[lc + 3][lr + 64] = b1.w;
        __syncthreads();
        if (k0 + 16 < CC) {
            a0 = *(const float4*)(xa + k0 + 16);
            a1 = *(const float4*)(xa + (size_t)64 * CC + k0 + 16);
            b0 = *(const float4*)(wb + k0 + 16);
            b1 = *(const float4*)(wb + (size_t)64 * CC + k0 + 16);
        }
#pragma unroll
        for (int kk = 0; kk < 16; kk++) {
            float4 ra0 = *(const float4*)&As[kk][ty * 4];
            float4 ra1 = *(const float4*)&As[kk][64 + ty * 4];
            u64 b2[4];
            b2[0] = *(const u64*)&Bs[kk][tx * 4];
            b2[1] = *(const u64*)&Bs[kk][tx * 4 + 2];
            b2[2] = *(const u64*)&Bs[kk][64 + tx * 4];
            b2[3] = *(const u64*)&Bs[kk][64 + tx * 4 + 2];
            u64 a2[8] = {splat2(ra0.x), splat2(ra0.y), splat2(ra0.z), splat2(ra0.w),
                         splat2(ra1.x), splat2(ra1.y), splat2(ra1.z), splat2(ra1.w)};
#pragma unroll
            for (int i = 0; i < 8; i++)
#pragma unroll
                for (int j = 0; j < 4; j++) fma2(acc[i][j], a2[i], b2[j]);
        }
    }

    // scatter: jj = t*768 + h*64 + d ; m = b*576 + n
#pragma unroll
    for (int i = 0; i < 8; i++) {
        int m = m0 + ((i < 4) ? (ty * 4 + i) : (64 + ty * 4 + i - 4));
        int b = m / NN, n = m % NN;
#pragma unroll
        for (int j2 = 0; j2 < 4; j2++) {
            float2 v = unpack2(acc[i][j2]);
            int cbase = (j2 < 2) ? (tx * 4 + j2 * 2) : (64 + tx * 4 + (j2 - 2) * 2);
#pragma unroll
            for (int p = 0; p < 2; p++) {
                int jj = j0 + cbase + p;
                float val = p ? v.y : v.x;
                int t = jj / CC;
                int r = jj - t * CC;
                int h = r >> 6;
                int d = r & 63;
                int idx = ((b * HH + h) * NN + n) * HDIM + d;
                if (t == 0)      g_q[idx] = val * SCALE;
                else if (t == 1) g_k[idx] = val;
                else             g_v[idx] = val;
            }
        }
    }
}

// ============================================================================
// Kernel 2: raw scores, pure batched GEMM S = Q K^T per (b,h).
// 64x64 tile, K=64 in one shot. 128 thr, 8x4/thread (f32x2 pairs along m).
// Smem transposed [d][m] / [d][n] so compute reads are b64/float4.
// Grid: (9, 9, 192)
// ============================================================================
__global__ __launch_bounds__(128) void score_kernel() {
    __shared__ float Qs[64][68];   // [d][m]
    __shared__ float Ks[64][68];   // [d][n]
    const int bh = blockIdx.z;
    const int m0 = blockIdx.y * 64;
    const int n0 = blockIdx.x * 64;
    const int tid = threadIdx.x;
    const int tx = tid & 15, ty = tid >> 4;       // tx: n/4, ty: m/8 (0..7)
    const int lr = tid & 63, half = tid >> 6;

    const float* qb = &g_q[((size_t)bh * NN + m0 + lr) * HDIM];
    const float* kb = &g_k[((size_t)bh * NN + n0 + lr) * HDIM];
#pragma unroll
    for (int i = 0; i < 8; i++) {
        int c = half * 32 + i * 4;
        float4 qv = *(const float4*)(qb + c);
        Qs[c + 0][lr] = qv.x; Qs[c + 1][lr] = qv.y; Qs[c + 2][lr] = qv.z; Qs[c + 3][lr] = qv.w;
        float4 kv = *(const float4*)(kb + c);
        Ks[c + 0][lr] = kv.x; Ks[c + 1][lr] = kv.y; Ks[c + 2][lr] = kv.z; Ks[c + 3][lr] = kv.w;
    }
    __syncthreads();

    u64 acc[4][4];
#pragma unroll
    for (int i = 0; i < 4; i++)
#pragma unroll
        for (int j = 0; j < 4; j++) acc[i][j] = 0ull;

#pragma unroll 16
    for (int kk = 0; kk < 64; kk++) {
        u64 a2[4];
        a2[0] = *(const u64*)&Qs[kk][ty * 4];
        a2[1] = *(const u64*)&Qs[kk][ty * 4 + 2];
        a2[2] = *(const u64*)&Qs[kk][32 + ty * 4];
        a2[3] = *(const u64*)&Qs[kk][32 + ty * 4 + 2];
        float4 bv = *(const float4*)&Ks[kk][tx * 4];
        u64 b2[4] = {splat2(bv.x), splat2(bv.y), splat2(bv.z), splat2(bv.w)};
#pragma unroll
        for (int i = 0; i < 4; i++)
#pragma unroll
            for (int j = 0; j < 4; j++) fma2(acc[i][j], a2[i], b2[j]);
    }

    float* outb = &g_attn[((size_t)bh * NN + m0) * NN + n0];
#pragma unroll
    for (int i2 = 0; i2 < 4; i2++) {
        int r0 = (i2 < 2) ? (ty * 4 + i2 * 2) : (32 + ty * 4 + (i2 - 2) * 2);
        float2 v0 = unpack2(acc[i2][0]);
        float2 v1 = unpack2(acc[i2][1]);
        float2 v2 = unpack2(acc[i2][2]);
        float2 v3 = unpack2(acc[i2][3]);
        *(float4*)&outb[(size_t)r0 * NN + tx * 4] = make_float4(v0.x, v1.x, v2.x, v3.x);
        *(float4*)&outb[(size_t)(r0 + 1) * NN + tx * 4] = make_float4(v0.y, v1.y, v2.y, v3.y);
    }
}

// ============================================================================
// Kernel 3: pre-mix (Wl,bl) + softmax + post-mix (Ww,bw), fused per (b,m).
// 384 threads = 12 warps (warp per head for softmax); mixes per n-column.
// ============================================================================
__global__ __launch_bounds__(384) void softmax_mix_kernel(const float* __restrict__ Wl,
                                                          const float* __restrict__ bl,
                                                          const float* __restrict__ Ww,
                                                          const float* __restrict__ bw) {
    __shared__ float sm[HH][NN];
    __shared__ float wls[HH * HH];
    __shared__ float bls[HH];
    __shared__ float wws[HH * HH];
    __shared__ float bws[HH];

    const int bm = blockIdx.x;
    const int b = bm / NN, m = bm % NN;
    const int tid = threadIdx.x;
    const int lane = tid & 31;
    const int wid = tid >> 5;

    if (tid < HH * HH) { wls[tid] = Wl[tid]; wws[tid] = Ww[tid]; }
    if (tid < HH) { bls[tid] = bl[tid]; bws[tid] = bw[tid]; }

    // load raw scores for all 12 heads of this row
    for (int idx = tid; idx < HH * NN; idx += 384) {
        int h = idx / NN, n = idx - h * NN;
        sm[h][n] = g_attn[(size_t)((b * HH + h) * NN + m) * NN + n];
    }
    __syncthreads();

    // pre-softmax mix (in-place per column: all reads buffered first)
    for (int n = tid; n < NN; n += 384) {
        float p[HH];
#pragma unroll
        for (int h = 0; h < HH; h++) p[h] = sm[h][n];
#pragma unroll
        for (int g = 0; g < HH; g++) {
            float o = bls[g];
#pragma unroll
            for (int h = 0; h < HH; h++) o += wls[g * HH + h] * p[h];
            sm[g][n] = o;
        }
    }
    __syncthreads();

    // softmax: warp w owns head w
    {
        const int h = wid;
        float mx = -1e30f;
        for (int n = lane; n < NN; n += 32) mx = fmaxf(mx, sm[h][n]);
#pragma unroll
        for (int o = 16; o > 0; o >>= 1) mx = fmaxf(mx, __shfl_xor_sync(0xffffffffu, mx, o));
        float sum = 0.f;
        for (int n = lane; n < NN; n += 32) {
            float e = __expf(sm[h][n] - mx);
            sm[h][n] = e;
            sum += e;
        }
#pragma unroll
        for (int o = 16; o > 0; o >>= 1) sum += __shfl_xor_sync(0xffffffffu, sum, o);
        float inv = 1.f / sum;
        for (int n = lane; n < NN; n += 32) sm[h][n] *= inv;
    }
    __syncthreads();

    // post-softmax mix + store
    for (int n = tid; n < NN; n += 384) {
        float p[HH];
#pragma unroll
        for (int h = 0; h < HH; h++) p[h] = sm[h][n];
#pragma unroll
        for (int g = 0; g < HH; g++) {
            float o = bws[g];
#pragma unroll
            for (int h = 0; h < HH; h++) o += wws[g * HH + h] * p[h];
            g_attn[(size_t)((b * HH + g) * NN + m) * NN + n] = o;
        }
    }
}

// ============================================================================
// Kernel 4: O = attn2 @ V per (b,h). 64m x 64d tile, k-loop over n (9x64),
// 128 thr, 8x4/thread (f32x2), smem [n][m]/[n][d], global->reg prefetch.
// Grid: (9, 192)
// ============================================================================
__global__ __launch_bounds__(128) void av_kernel() {
    __shared__ float As[64][68];   // [n][m]
    __shared__ float Vs[64][64];   // [n][d]
    const int bh = blockIdx.y;
    const int m0 = blockIdx.x * 64;
    const int tid = threadIdx.x;
    const int tx = tid & 15, ty = tid >> 4;
    const int lr = tid & 63, half = tid >> 6;       // A-tile mapping
    const int vlr = tid >> 1, vhalf = tid & 1;      // V-tile mapping

    const float* Ab = &g_attn[((size_t)bh * NN + m0 + lr) * NN];
    const float* Vbase = &g_v[(size_t)bh * NN * HDIM];

    u64 acc[4][4];
#pragma unroll
    for (int i = 0; i < 4; i++)
#pragma unroll
        for (int j = 0; j < 4; j++) acc[i][j] = 0ull;

    float4 ar[8], vr[8];
#pragma unroll
    for (int i = 0; i < 8; i++) {
        ar[i] = *(const float4*)&Ab[half * 32 + i * 4];
        vr[i] = *(const float4*)&Vbase[(size_t)vlr * HDIM + vhalf * 32 + i * 4];
    }

    for (int c = 0; c < 9; c++) {
        __syncthreads();
#pragma unroll
        for (int i = 0; i < 8; i++) {
            int cc = half * 32 + i * 4;
            As[cc + 0][lr] = ar[i].x; As[cc + 1][lr] = ar[i].y;
            As[cc + 2][lr] = ar[i].z; As[cc + 3][lr] = ar[i].w;
            *(float4*)&Vs[vlr][vhalf * 32 + i * 4] = vr[i];
        }
        __syncthreads();
        if (c < 8) {
            int n0 = (c + 1) * 64;
#pragma unroll
            for (int i = 0; i < 8; i++) {
                ar[i] = *(const float4*)&Ab[n0 + half * 32 + i * 4];
                vr[i] = *(const float4*)&Vbase[(size_t)(n0 + vlr) * HDIM + vhalf * 32 + i * 4];
            }
        }
#pragma unroll 16
        for (int kk = 0; kk < 64; kk++) {
            u64 a2[4];
            a2[0] = *(const u64*)&As[kk][ty * 4];
            a2[1] = *(const u64*)&As[kk][ty * 4 + 2];
            a2[2] = *(const u64*)&As[kk][32 + ty * 4];
            a2[3] = *(const u64*)&As[kk][32 + ty * 4 + 2];
            float4 bv = *(const float4*)&Vs[kk][tx * 4];
            u64 b2[4] = {splat2(bv.x), splat2(bv.y), splat2(bv.z), splat2(bv.w)};
#pragma unroll
            for (int i = 0; i < 4; i++)
#pragma unroll
                for (int j = 0; j < 4; j++) fma2(acc[i][j], a2[i], b2[j]);
        }
    }

    float* ob = &g_o1[((size_t)(bh / HH) * NN + m0) * CC + (bh % HH) * HDIM];
#pragma unroll
    for (int i2 = 0; i2 < 4; i2++) {
        int r0 = (i2 < 2) ? (ty * 4 + i2 * 2) : (32 + ty * 4 + (i2 - 2) * 2);
        float2 v0 = unpack2(acc[i2][0]);
        float2 v1 = unpack2(acc[i2][1]);
        float2 v2 = unpack2(acc[i2][2]);
        float2 v3 = unpack2(acc[i2][3]);
        *(float4*)&ob[(size_t)r0 * CC + tx * 4] = make_float4(v0.x, v1.x, v2.x, v3.x);
        *(float4*)&ob[(size_t)(r0 + 1) * CC + tx * 4] = make_float4(v0.y, v1.y, v2.y, v3.y);
    }
}

// ============================================================================
// Kernel 5: out = o1 @ Wproj^T + bproj. Same scheme as kernel 1, f32x2.
// Grid: (6, 72)
// ============================================================================
__global__ __launch_bounds__(256) void proj_kernel(const float* __restrict__ W,
                                                   const float* __restrict__ bias,
                                                   float* __restrict__ out) {
    __shared__ float As[16][128];
    __shared__ float Bs[16][128];
    const int m0 = blockIdx.y * 128;
    const int j0 = blockIdx.x * 128;
    const int tid = threadIdx.x;
    const int tx = tid & 15, ty = tid >> 4;
    const int lr = tid >> 2;
    const int lc = (tid & 3) << 2;

    u64 acc[8][4];
#pragma unroll
    for (int i = 0; i < 8; i++)
#pragma unroll
        for (int j = 0; j < 4; j++) acc[i][j] = 0ull;

    const float* xa = &g_o1[(size_t)(m0 + lr) * CC + lc];
    const float* wb = &W[(size_t)(j0 + lr) * CC + lc];

    float4 a0 = *(const float4*)xa;
    float4 a1 = *(const float4*)(xa + (size_t)64 * CC);
    float4 b0 = *(const float4*)wb;
    float4 b1 = *(const float4*)(wb + (size_t)64 * CC);

    for (int k0 = 0; k0 < CC; k0 += 16) {
        __syncthreads();
        As[lc + 0][lr] = a0.x; As[lc + 1][lr] = a0.y; As[lc + 2][lr] = a0.z; As[lc + 3][lr] = a0.w;
        As[lc + 0][lr + 64] = a1.x; As[lc + 1][lr + 64] = a1.y; As[lc + 2][lr + 64] = a1.z; As[lc + 3][lr + 64] = a1.w;
        Bs[lc + 0][lr] = b0.x; Bs[lc + 1][lr] = b0.y; Bs[lc + 2][lr] = b0.z; Bs[lc + 3][lr] = b0.w;
        Bs[lc + 0][lr + 64] = b1.x; Bs[lc + 1][lr + 64] = b1.y; Bs[lc + 2][lr + 64] = b1.z; Bs[lc + 3][lr + 64] = b1.w;
        __syncthreads();
        if (k0 + 16 < CC) {
            a0 = *(const float4*)(xa + k0 + 16);
            a1 = *(const float4*)(xa + (size_t)64 * CC + k0 + 16);
            b0 = *(const float4*)(wb + k0 + 16);
            b1 = *(const float4*)(wb + (size_t)64 * CC + k0 + 16);
        }
#pragma unroll
        for (int kk = 0; kk < 16; kk++) {
            float4 ra0 = *(const float4*)&As[kk][ty * 4];
            float4 ra1 = *(const float4*)&As[kk][64 + ty * 4];
            u64 b2[4];
            b2[0] = *(const u64*)&Bs[kk][tx * 4];
            b2[1] = *(const u64*)&Bs[kk][tx * 4 + 2];
            b2[2] = *(const u64*)&Bs[kk][64 + tx * 4];
            b2[3] = *(const u64*)&Bs[kk][64 + tx * 4 + 2];
            u64 a2[8] = {splat2(ra0.x), splat2(ra0.y), splat2(ra0.z), splat2(ra0.w),
                         splat2(ra1.x), splat2(ra1.y), splat2(ra1.z), splat2(ra1.w)};
#pragma unroll
            for (int i = 0; i < 8; i++)
#pragma unroll
                for (int j = 0; j < 4; j++) fma2(acc[i][j], a2[i], b2[j]);
        }
    }

    float4 bv0 = *(const float4*)&bias[j0 + tx * 4];
    float4 bv1 = *(const float4*)&bias[j0 + 64 + tx * 4];
#pragma unroll
    for (int i = 0; i < 8; i++) {
        int m = m0 + ((i < 4) ? (ty * 4 + i) : (64 + ty * 4 + i - 4));
        float2 p0 = unpack2(acc[i][0]);
        float2 p1 = unpack2(acc[i][1]);
        float2 p2 = unpack2(acc[i][2]);
        float2 p3 = unpack2(acc[i][3]);
        *(float4*)&out[(size_t)m * CC + j0 + tx * 4] =
            make_float4(p0.x + bv0.x, p0.y + bv0.y, p1.x + bv0.z, p1.y + bv0.w);
        *(float4*)&out[(size_t)m * CC + j0 + 64 + tx * 4] =
            make_float4(p2.x + bv1.x, p2.y + bv1.y, p3.x + bv1.z, p3.y + bv1.w);
    }
}

// ============================================================================
extern "C" void kernel_launch(void* const* d_in, const int* in_sizes, int n_in,
                              void* d_out, int out_size) {
    const float* x     = (const float*)d_in[0];
    const float* Wqkv  = (const float*)d_in[1];
    const float* Wl    = (const float*)d_in[2];
    const float* bl    = (const float*)d_in[3];
    const float* Ww    = (const float*)d_in[4];
    const float* bw    = (const float*)d_in[5];
    const float* Wproj = (const float*)d_in[6];
    const float* bproj = (const float*)d_in[7];
    float* out = (float*)d_out;

    qkv_kernel<<<dim3(18, 72), 256>>>(x, Wqkv);
    score_kernel<<<dim3(9, 9, 192), 128>>>();
    softmax_mix_kernel<<<MTOT, 384>>>(Wl, bl, Ww, bw);
    av_kernel<<<dim3(9, 192), 128>>>();
    proj_kernel<<<dim3(6, 72), 256>>>(Wproj, bproj, out);
}

// round 5
// speedup vs baseline: 1.8843x; 1.6933x over previous
#include <cuda_runtime.h>
#include <cuda_bf16.h>

// Talking-heads attention via mma.sync bf16 tensor cores (plain sm_100 ISA).
// All GEMMs: bf16 hi/lo split (3 MMAs) -> fp32-class accuracy, fp32 accumulators.
// B=16, N=576, C=768, H=12, HD=64.

#define BB 16
#define NN 576
#define CC 768
#define HH 12
#define HDIM 64
#define MTOT (BB * NN)
#define SCALE 0.125f
#define ATT ((size_t)BB * HH * NN * NN)
#define QKE (BB * HH * NN * HDIM)

typedef unsigned int u32;

// ============================ PTX helpers (sm_80+ ISA only) ============================
__device__ __forceinline__ u32 smem_u32(const void* p) {
    u32 a;
    asm("{ .reg .u64 t; cvta.to.shared.u64 t, %1; cvt.u32.u64 %0, t; }" : "=r"(a) : "l"(p));
    return a;
}
__device__ __forceinline__ void cp16(u32 dst, const void* src) {
    asm volatile("cp.async.cg.shared.global [%0], [%1], 16;" :: "r"(dst), "l"(src));
}
__device__ __forceinline__ void cp_commit() {
    asm volatile("cp.async.commit_group;" ::: "memory");
}
template <int N>
__device__ __forceinline__ void cp_wait() {
    asm volatile("cp.async.wait_group %0;" :: "n"(N) : "memory");
}
__device__ __forceinline__ void ldm_x4(u32 a, u32& r0, u32& r1, u32& r2, u32& r3) {
    asm volatile("ldmatrix.sync.aligned.m8n8.x4.shared.b16 {%0,%1,%2,%3}, [%4];"
                 : "=r"(r0), "=r"(r1), "=r"(r2), "=r"(r3) : "r"(a));
}
__device__ __forceinline__ void mma_bf16(float* d, const u32* a, const u32* b) {
    asm volatile("mma.sync.aligned.m16n8k16.row.col.f32.bf16.bf16.f32 "
                 "{%0,%1,%2,%3}, {%4,%5,%6,%7}, {%8,%9}, {%0,%1,%2,%3};"
                 : "+f"(d[0]), "+f"(d[1]), "+f"(d[2]), "+f"(d[3])
                 : "r"(a[0]), "r"(a[1]), "r"(a[2]), "r"(a[3]), "r"(b[0]), "r"(b[1]));
}

// ============================ scratch (16B-aligned) ============================
__device__ __align__(16) __nv_bfloat16 g_xh[MTOT * CC], g_xl[MTOT * CC];
__device__ __align__(16) __nv_bfloat16 g_wqh[3 * CC * CC], g_wql[3 * CC * CC];
__device__ __align__(16) __nv_bfloat16 g_wph[CC * CC], g_wpl[CC * CC];
__device__ __align__(16) __nv_bfloat16 g_qh[QKE + 64 * HDIM], g_ql[QKE + 64 * HDIM];
__device__ __align__(16) __nv_bfloat16 g_kh[QKE + 64 * HDIM], g_kl[QKE + 64 * HDIM];
__device__ __align__(16) __nv_bfloat16 g_vh[QKE], g_vl[QKE];
__device__ __align__(16) __nv_bfloat16 g_vth[QKE], g_vtl[QKE];
__device__ __align__(16) float g_attn[ATT];
__device__ __align__(16) __nv_bfloat16 g_a2h[ATT + 64 * NN], g_a2l[ATT + 64 * NN];
__device__ __align__(16) __nv_bfloat16 g_o1h[MTOT * CC], g_o1l[MTOT * CC];

__device__ __forceinline__ u32 pack_hi_lo(float f0, float f1, u32& lo_out) {
    __nv_bfloat16 h0 = __float2bfloat16(f0);
    __nv_bfloat16 h1 = __float2bfloat16(f1);
    __nv_bfloat16 l0 = __float2bfloat16(f0 - __bfloat162float(h0));
    __nv_bfloat16 l1 = __float2bfloat16(f1 - __bfloat162float(h1));
    u32 hw = ((u32)__bfloat16_as_ushort(h1) << 16) | __bfloat16_as_ushort(h0);
    lo_out = ((u32)__bfloat16_as_ushort(l1) << 16) | __bfloat16_as_ushort(l0);
    return hw;
}

// ============================ core GEMM mainloop ============================
// C[m,n] = sum_k A[m,k]*B[n,k]; A,B bf16 hi/lo row-major with k contiguous.
// BM x BN tile, BK=32, 256 threads, TMW x TNW warps, warp tile 32x32.
// Smem: XOR-swizzled 64B rows, conflict-free ldmatrix; double-buffered cp.async.
// Smem bytes: 2*(2*BM + 2*BN)*64  (49152 for BM=128, BN=64).
template <int BM, int BN, int TMW, int TNW>
__device__ __forceinline__ void gemm_core(
    const __nv_bfloat16* __restrict__ Ah, const __nv_bfloat16* __restrict__ Al, int lda,
    const __nv_bfloat16* __restrict__ Bh, const __nv_bfloat16* __restrict__ Bl, int ldb,
    int K, u32 sb, float (*acc)[4][4]) {
    constexpr int MI = BM / TMW / 16;
    constexpr int NI = BN / TNW / 8;
    static_assert(NI == 4, "epilogue layout assumes NI==4");
    constexpr u32 OFF_AL = BM * 64;
    constexpr u32 OFF_BH = 2 * BM * 64;
    constexpr u32 OFF_BL = 2 * BM * 64 + BN * 64;
    constexpr u32 SS = (2 * BM + 2 * BN) * 64;
    const int tid = threadIdx.x;
    const int lane = tid & 31, wid = tid >> 5;
    const int wrow = (wid / TNW) * (BM / TMW);
    const int wcol = (wid % TNW) * (BN / TNW);
    const int NK = K >> 5;

    auto issue = [&](int kt) {
        const u32 st = sb + (u32)(kt & 1) * SS;
        const int k0 = kt << 5;
#pragma unroll
        for (int i = tid; i < BM * 4; i += 256) {
            int r = i >> 2, c = i & 3;
            u32 doff = (u32)(r * 64 + ((c ^ ((r >> 1) & 3)) << 4));
            cp16(st + doff, Ah + (size_t)r * lda + k0 + c * 8);
            cp16(st + OFF_AL + doff, Al + (size_t)r * lda + k0 + c * 8);
        }
#pragma unroll
        for (int i = tid; i < BN * 4; i += 256) {
            int r = i >> 2, c = i & 3;
            u32 doff = (u32)(r * 64 + ((c ^ ((r >> 1) & 3)) << 4));
            cp16(st + OFF_BH + doff, Bh + (size_t)r * ldb + k0 + c * 8);
            cp16(st + OFF_BL + doff, Bl + (size_t)r * ldb + k0 + c * 8);
        }
        cp_commit();
    };

    issue(0);
    for (int kt = 0; kt < NK; kt++) {
        if (kt + 1 < NK) { issue(kt + 1); cp_wait<1>(); }
        else             { cp_wait<0>(); }
        __syncthreads();
        const u32 st = sb + (u32)(kt & 1) * SS;
#pragma unroll
        for (int ks = 0; ks < 2; ks++) {
            u32 ah[MI][4], al[MI][4], bh[NI][2], bl[NI][2];
            {
                const int kc = ks * 2 + (lane >> 4);           // A k-chunk 0..3
#pragma unroll
                for (int mi = 0; mi < MI; mi++) {
                    int r = wrow + mi * 16 + (lane & 15);
                    u32 a = st + (u32)(r * 64 + ((kc ^ ((r >> 1) & 3)) << 4));
                    ldm_x4(a, ah[mi][0], ah[mi][1], ah[mi][2], ah[mi][3]);
                    ldm_x4(a + OFF_AL, al[mi][0], al[mi][1], al[mi][2], al[mi][3]);
                }
            }
            {
                const int kc = ks * 2 + ((lane >> 3) & 1);     // B k-chunk
                const int rb = wcol + ((lane >> 4) << 3) + (lane & 7);
#pragma unroll
                for (int ni = 0; ni < NI; ni += 2) {
                    int r = rb + ni * 8;
                    u32 swz = (u32)(r * 64 + ((kc ^ ((r >> 1) & 3)) << 4));
                    ldm_x4(st + OFF_BH + swz, bh[ni][0], bh[ni][1], bh[ni + 1][0], bh[ni + 1][1]);
                    ldm_x4(st + OFF_BL + swz, bl[ni][0], bl[ni][1], bl[ni + 1][0], bl[ni + 1][1]);
                }
            }
#pragma unroll
            for (int mi = 0; mi < MI; mi++)
#pragma unroll
                for (int ni = 0; ni < NI; ni++) {
                    mma_bf16(acc[mi][ni], ah[mi], bh[ni]);   // hi*hi
                    mma_bf16(acc[mi][ni], ah[mi], bl[ni]);   // hi*lo
                    mma_bf16(acc[mi][ni], al[mi], bh[ni]);   // lo*hi
                }
        }
        __syncthreads();
    }
}

#define GEMM_SMEM 49152

// ============================ fp32 -> bf16 hi/lo split ============================
__global__ __launch_bounds__(256) void split_kernel(const float* __restrict__ in,
                                                    __nv_bfloat16* __restrict__ hi,
                                                    __nv_bfloat16* __restrict__ lo, int n) {
    int i = (blockIdx.x * 256 + threadIdx.x) * 4;
    if (i >= n) return;
    float4 v = *reinterpret_cast<const float4*>(in + i);
    u32 l0, l1;
    u32 h0 = pack_hi_lo(v.x, v.y, l0);
    u32 h1 = pack_hi_lo(v.z, v.w, l1);
    *reinterpret_cast<uint2*>(hi + i) = make_uint2(h0, h1);
    *reinterpret_cast<uint2*>(lo + i) = make_uint2(l0, l1);
}

// ============================ QKV GEMM + scatter ============================
// grid (2304/64=36, 9216/128=72)
__global__ __launch_bounds__(256) void qkv_mma() {
    extern __shared__ char smem[];
    u32 sb = smem_u32(smem);
    const int n0 = blockIdx.x * 64, m0 = blockIdx.y * 128;
    float acc[2][4][4];
#pragma unroll
    for (int i = 0; i < 2; i++)
#pragma unroll
        for (int j = 0; j < 4; j++)
#pragma unroll
            for (int k = 0; k < 4; k++) acc[i][j][k] = 0.f;
    gemm_core<128, 64, 4, 2>(g_xh + (size_t)m0 * CC, g_xl + (size_t)m0 * CC, CC,
                             g_wqh + (size_t)n0 * CC, g_wql + (size_t)n0 * CC, CC,
                             CC, sb, acc);
    const int tid = threadIdx.x, lane = tid & 31, wid = tid >> 5;
    const int wm = wid >> 1, wn = wid & 1;
#pragma unroll
    for (int mi = 0; mi < 2; mi++)
#pragma unroll
        for (int ni = 0; ni < 4; ni++) {
            int c = n0 + wn * 32 + ni * 8 + (lane & 3) * 2;
            int t = c / CC, rc = c - t * CC, h = rc >> 6, d0 = rc & 63;
            float sc = (t == 0) ? SCALE : 1.f;
            __nv_bfloat16* ph = (t == 0) ? g_qh : (t == 1) ? g_kh : g_vh;
            __nv_bfloat16* pl = (t == 0) ? g_ql : (t == 1) ? g_kl : g_vl;
#pragma unroll
            for (int hf = 0; hf < 2; hf++) {
                int m = m0 + wm * 32 + mi * 16 + (lane >> 2) + hf * 8;
                int b = m / NN, ntok = m - b * NN;
                size_t base = ((size_t)(b * HH + h) * NN + ntok) * HDIM + d0;
                u32 lw, hw = pack_hi_lo(acc[mi][ni][hf * 2] * sc, acc[mi][ni][hf * 2 + 1] * sc, lw);
                *reinterpret_cast<u32*>(ph + base) = hw;
                *reinterpret_cast<u32*>(pl + base) = lw;
            }
        }
}

// ============================ transpose V -> vT[d][n] ============================
__global__ __launch_bounds__(256) void transpose_v() {
    __shared__ __nv_bfloat16 th[32][33], tl[32][33];
    int n0 = blockIdx.x * 32, d0 = blockIdx.y * 32, bh = blockIdx.z;
    int tx = threadIdx.x, ty = threadIdx.y;
#pragma unroll
    for (int i = 0; i < 4; i++) {
        int n = n0 + ty + i * 8;
        size_t s = ((size_t)bh * NN + n) * HDIM + d0 + tx;
        th[ty + i * 8][tx] = g_vh[s];
        tl[ty + i * 8][tx] = g_vl[s];
    }
    __syncthreads();
#pragma unroll
    for (int i = 0; i < 4; i++) {
        int d = d0 + ty + i * 8;
        size_t t = ((size_t)bh * HDIM + d) * NN + n0 + tx;
        g_vth[t] = th[tx][ty + i * 8];
        g_vtl[t] = tl[tx][ty + i * 8];
    }
}

// ============================ score GEMM S = Q K^T per (b,h) ============================
// grid (9, 5, 192)
__global__ __launch_bounds__(256) void score_mma() {
    extern __shared__ char smem[];
    u32 sb = smem_u32(smem);
    const int n0 = blockIdx.x * 64, m0 = blockIdx.y * 128, bh = blockIdx.z;
    float acc[2][4][4];
#pragma unroll
    for (int i = 0; i < 2; i++)
#pragma unroll
        for (int j = 0; j < 4; j++)
#pragma unroll
            for (int k = 0; k < 4; k++) acc[i][j][k] = 0.f;
    const size_t ab = ((size_t)bh * NN + m0) * HDIM;
    const size_t bb = ((size_t)bh * NN + n0) * HDIM;
    gemm_core<128, 64, 4, 2>(g_qh + ab, g_ql + ab, HDIM,
                             g_kh + bb, g_kl + bb, HDIM, HDIM, sb, acc);
    const int tid = threadIdx.x, lane = tid & 31, wid = tid >> 5;
    const int wm = wid >> 1, wn = wid & 1;
    float* outb = g_attn + (size_t)bh * NN * NN;
#pragma unroll
    for (int mi = 0; mi < 2; mi++)
#pragma unroll
        for (int ni = 0; ni < 4; ni++) {
            int c = n0 + wn * 32 + ni * 8 + (lane & 3) * 2;
#pragma unroll
            for (int hf = 0; hf < 2; hf++) {
                int m = m0 + wm * 32 + mi * 16 + (lane >> 2) + hf * 8;
                if (m < NN)
                    *reinterpret_cast<float2*>(outb + (size_t)m * NN + c) =
                        make_float2(acc[mi][ni][hf * 2], acc[mi][ni][hf * 2 + 1]);
            }
        }
}

// ============================ softmax + both talking-heads mixes ============================
__global__ __launch_bounds__(384) void softmax_mix_kernel(const float* __restrict__ Wl,
                                                          const float* __restrict__ bl,
                                                          const float* __restrict__ Ww,
                                                          const float* __restrict__ bw) {
    __shared__ float sm[HH][NN];
    __shared__ float wls[HH * HH], bls[HH], wws[HH * HH], bws[HH];
    const int bm = blockIdx.x;
    const int b = bm / NN, m = bm % NN;
    const int tid = threadIdx.x, lane = tid & 31, wid = tid >> 5;

    if (tid < HH * HH) { wls[tid] = Wl[tid]; wws[tid] = Ww[tid]; }
    if (tid < HH) { bls[tid] = bl[tid]; bws[tid] = bw[tid]; }

    for (int idx = tid; idx < HH * NN; idx += 384) {
        int h = idx / NN, n = idx - h * NN;
        sm[h][n] = g_attn[((size_t)(b * HH + h) * NN + m) * NN + n];
    }
    __syncthreads();

    for (int n = tid; n < NN; n += 384) {
        float p[HH];
#pragma unroll
        for (int h = 0; h < HH; h++) p[h] = sm[h][n];
#pragma unroll
        for (int g = 0; g < HH; g++) {
            float o = bls[g];
#pragma unroll
            for (int h = 0; h < HH; h++) o += wls[g * HH + h] * p[h];
            sm[g][n] = o;
        }
    }
    __syncthreads();

    {
        const int h = wid;
        float mx = -1e30f;
        for (int n = lane; n < NN; n += 32) mx = fmaxf(mx, sm[h][n]);
#pragma unroll
        for (int o = 16; o > 0; o >>= 1) mx = fmaxf(mx, __shfl_xor_sync(0xffffffffu, mx, o));
        float sum = 0.f;
        for (int n = lane; n < NN; n += 32) {
            float e = __expf(sm[h][n] - mx);
            sm[h][n] = e; sum += e;
        }
#pragma unroll
        for (int o = 16; o > 0; o >>= 1) sum += __shfl_xor_sync(0xffffffffu, sum, o);
        float inv = 1.f / sum;
        for (int n = lane; n < NN; n += 32) sm[h][n] *= inv;
    }
    __syncthreads();

    for (int n2 = tid; n2 < NN / 2; n2 += 384) {
        int n = n2 * 2;
        float p0[HH], p1[HH];
#pragma unroll
        for (int h = 0; h < HH; h++) { p0[h] = sm[h][n]; p1[h] = sm[h][n + 1]; }
#pragma unroll
        for (int g = 0; g < HH; g++) {
            float o0 = bws[g], o1 = bws[g];
#pragma unroll
            for (int h = 0; h < HH; h++) { o0 += wws[g * HH + h] * p0[h]; o1 += wws[g * HH + h] * p1[h]; }
            size_t idx = ((size_t)(b * HH + g) * NN + m) * NN + n;
            u32 lw, hw = pack_hi_lo(o0, o1, lw);
            *reinterpret_cast<u32*>(g_a2h + idx) = hw;
            *reinterpret_cast<u32*>(g_a2l + idx) = lw;
        }
    }
}

// ============================ O = attn2 @ V per (b,h) ============================
// grid (5, 192). K = 576.
__global__ __launch_bounds__(256) void av_mma() {
    extern __shared__ char smem[];
    u32 sb = smem_u32(smem);
    const int m0 = blockIdx.x * 128, bh = blockIdx.y;
    float acc[2][4][4];
#pragma unroll
    for (int i = 0; i < 2; i++)
#pragma unroll
        for (int j = 0; j < 4; j++)
#pragma unroll
            for (int k = 0; k < 4; k++) acc[i][j][k] = 0.f;
    const size_t ab = (size_t)bh * NN * NN + (size_t)m0 * NN;
    const size_t bb = (size_t)bh * HDIM * NN;
    gemm_core<128, 64, 4, 2>(g_a2h + ab, g_a2l + ab, NN,
                             g_vth + bb, g_vtl + bb, NN, NN, sb, acc);
    const int tid = threadIdx.x, lane = tid & 31, wid = tid >> 5;
    const int wm = wid >> 1, wn = wid & 1;
    const int b = bh / HH, h = bh - b * HH;
#pragma unroll
    for (int mi = 0; mi < 2; mi++)
#pragma unroll
        for (int ni = 0; ni < 4; ni++) {
            int dc = wn * 32 + ni * 8 + (lane & 3) * 2;
#pragma unroll
            for (int hf = 0; hf < 2; hf++) {
                int m = m0 + wm * 32 + mi * 16 + (lane >> 2) + hf * 8;
                if (m < NN) {
                    size_t base = ((size_t)b * NN + m) * CC + h * HDIM + dc;
                    u32 lw, hw = pack_hi_lo(acc[mi][ni][hf * 2], acc[mi][ni][hf * 2 + 1], lw);
                    *reinterpret_cast<u32*>(g_o1h + base) = hw;
                    *reinterpret_cast<u32*>(g_o1l + base) = lw;
                }
            }
        }
}

// ============================ out = o1 @ Wproj^T + bias ============================
// grid (12, 72)
__global__ __launch_bounds__(256) void proj_mma(const float* __restrict__ bias,
                                                float* __restrict__ out) {
    extern __shared__ char smem[];
    u32 sb = smem_u32(smem);
    const int n0 = blockIdx.x * 64, m0 = blockIdx.y * 128;
    float acc[2][4][4];
#pragma unroll
    for (int i = 0; i < 2; i++)
#pragma unroll
        for (int j = 0; j < 4; j++)
#pragma unroll
            for (int k = 0; k < 4; k++) acc[i][j][k] = 0.f;
    gemm_core<128, 64, 4, 2>(g_o1h + (size_t)m0 * CC, g_o1l + (size_t)m0 * CC, CC,
                             g_wph + (size_t)n0 * CC, g_wpl + (size_t)n0 * CC, CC,
                             CC, sb, acc);
    const int tid = threadIdx.x, lane = tid & 31, wid = tid >> 5;
    const int wm = wid >> 1, wn = wid & 1;
#pragma unroll
    for (int mi = 0; mi < 2; mi++)
#pragma unroll
        for (int ni = 0; ni < 4; ni++) {
            int c = n0 + wn * 32 + ni * 8 + (lane & 3) * 2;
            float b0 = __ldg(&bias[c]), b1 = __ldg(&bias[c + 1]);
#pragma unroll
            for (int hf = 0; hf < 2; hf++) {
                int m = m0 + wm * 32 + mi * 16 + (lane >> 2) + hf * 8;
                *reinterpret_cast<float2*>(out + (size_t)m * CC + c) =
                    make_float2(acc[mi][ni][hf * 2] + b0, acc[mi][ni][hf * 2 + 1] + b1);
            }
        }
}

// ============================ launch ============================
extern "C" void kernel_launch(void* const* d_in, const int* in_sizes, int n_in,
                              void* d_out, int out_size) {
    const float* x     = (const float*)d_in[0];
    const float* Wqkv  = (const float*)d_in[1];
    const float* Wl    = (const float*)d_in[2];
    const float* bl    = (const float*)d_in[3];
    const float* Ww    = (const float*)d_in[4];
    const float* bw    = (const float*)d_in[5];
    const float* Wproj = (const float*)d_in[6];
    const float* bproj = (const float*)d_in[7];
    float* out = (float*)d_out;

    __nv_bfloat16 *xh, *xl, *wqh, *wql, *wph, *wpl;
    cudaGetSymbolAddress((void**)&xh, g_xh);   cudaGetSymbolAddress((void**)&xl, g_xl);
    cudaGetSymbolAddress((void**)&wqh, g_wqh); cudaGetSymbolAddress((void**)&wql, g_wql);
    cudaGetSymbolAddress((void**)&wph, g_wph); cudaGetSymbolAddress((void**)&wpl, g_wpl);

    split_kernel<<<(MTOT * CC / 4 + 255) / 256, 256>>>(x, xh, xl, MTOT * CC);
    split_kernel<<<(3 * CC * CC / 4 + 255) / 256, 256>>>(Wqkv, wqh, wql, 3 * CC * CC);
    split_kernel<<<(CC * CC / 4 + 255) / 256, 256>>>(Wproj, wph, wpl, CC * CC);

    qkv_mma<<<dim3(36, 72), 256, GEMM_SMEM>>>();
    transpose_v<<<dim3(18, 2, BB * HH), dim3(32, 8)>>>();
    score_mma<<<dim3(9, 5, BB * HH), 256, GEMM_SMEM>>>();
    softmax_mix_kernel<<<MTOT, 384>>>(Wl, bl, Ww, bw);
    av_mma<<<dim3(5, BB * HH), 256, GEMM_SMEM>>>();
    proj_mma<<<dim3(12, 72), 256, GEMM_SMEM>>>(bproj, out);
}

// round 6
// speedup vs baseline: 2.5605x; 1.3588x over previous
#include <cuda_runtime.h>
#include <cuda_bf16.h>

// Talking-heads attention via mma.sync bf16 tensor cores (plain sm_100 ISA).
// All GEMMs: bf16 hi/lo split (3 MMAs) -> fp32-class accuracy, fp32 accumulators.
// v6: 3-stage cp.async pipeline, one barrier per k-tile; vectorized softmax IO.

#define BB 16
#define NN 576
#define CC 768
#define HH 12
#define HDIM 64
#define MTOT (BB * NN)
#define SCALE 0.125f
#define ATT ((size_t)BB * HH * NN * NN)
#define QKE (BB * HH * NN * HDIM)

typedef unsigned int u32;

// ============================ PTX helpers (sm_80+ ISA only) ============================
__device__ __forceinline__ u32 smem_u32(const void* p) {
    u32 a;
    asm("{ .reg .u64 t; cvta.to.shared.u64 t, %1; cvt.u32.u64 %0, t; }" : "=r"(a) : "l"(p));
    return a;
}
__device__ __forceinline__ void cp16(u32 dst, const void* src) {
    asm volatile("cp.async.cg.shared.global [%0], [%1], 16;" :: "r"(dst), "l"(src));
}
__device__ __forceinline__ void cp_commit() {
    asm volatile("cp.async.commit_group;" ::: "memory");
}
template <int N>
__device__ __forceinline__ void cp_wait() {
    asm volatile("cp.async.wait_group %0;" :: "n"(N) : "memory");
}
__device__ __forceinline__ void ldm_x4(u32 a, u32& r0, u32& r1, u32& r2, u32& r3) {
    asm volatile("ldmatrix.sync.aligned.m8n8.x4.shared.b16 {%0,%1,%2,%3}, [%4];"
                 : "=r"(r0), "=r"(r1), "=r"(r2), "=r"(r3) : "r"(a));
}
__device__ __forceinline__ void mma_bf16(float* d, const u32* a, const u32* b) {
    asm volatile("mma.sync.aligned.m16n8k16.row.col.f32.bf16.bf16.f32 "
                 "{%0,%1,%2,%3}, {%4,%5,%6,%7}, {%8,%9}, {%0,%1,%2,%3};"
                 : "+f"(d[0]), "+f"(d[1]), "+f"(d[2]), "+f"(d[3])
                 : "r"(a[0]), "r"(a[1]), "r"(a[2]), "r"(a[3]), "r"(b[0]), "r"(b[1]));
}

// ============================ scratch (16B-aligned) ============================
__device__ __align__(16) __nv_bfloat16 g_xh[MTOT * CC], g_xl[MTOT * CC];
__device__ __align__(16) __nv_bfloat16 g_wqh[3 * CC * CC], g_wql[3 * CC * CC];
__device__ __align__(16) __nv_bfloat16 g_wph[CC * CC], g_wpl[CC * CC];
__device__ __align__(16) __nv_bfloat16 g_qh[QKE + 64 * HDIM], g_ql[QKE + 64 * HDIM];
__device__ __align__(16) __nv_bfloat16 g_kh[QKE + 64 * HDIM], g_kl[QKE + 64 * HDIM];
__device__ __align__(16) __nv_bfloat16 g_vh[QKE], g_vl[QKE];
__device__ __align__(16) __nv_bfloat16 g_vth[QKE], g_vtl[QKE];
__device__ __align__(16) float g_attn[ATT];
__device__ __align__(16) __nv_bfloat16 g_a2h[ATT + 64 * NN], g_a2l[ATT + 64 * NN];
__device__ __align__(16) __nv_bfloat16 g_o1h[MTOT * CC], g_o1l[MTOT * CC];

__device__ __forceinline__ u32 pack_hi_lo(float f0, float f1, u32& lo_out) {
    __nv_bfloat16 h0 = __float2bfloat16(f0);
    __nv_bfloat16 h1 = __float2bfloat16(f1);
    __nv_bfloat16 l0 = __float2bfloat16(f0 - __bfloat162float(h0));
    __nv_bfloat16 l1 = __float2bfloat16(f1 - __bfloat162float(h1));
    u32 hw = ((u32)__bfloat16_as_ushort(h1) << 16) | __bfloat16_as_ushort(h0);
    lo_out = ((u32)__bfloat16_as_ushort(l1) << 16) | __bfloat16_as_ushort(l0);
    return hw;
}

// ============================ core GEMM mainloop (3-stage pipeline) ============================
// C[m,n] = sum_k A[m,k]*B[n,k]; A,B bf16 hi/lo row-major with k contiguous.
// BM x BN tile, BK=32, 256 threads, TMW x TNW warps, warp tile 32x32.
// Smem: XOR-swizzled 64B rows; 3-stage cp.async ring; ONE __syncthreads per k-tile.
template <int BM, int BN, int TMW, int TNW>
__device__ __forceinline__ void gemm_core(
    const __nv_bfloat16* __restrict__ Ah, const __nv_bfloat16* __restrict__ Al, int lda,
    const __nv_bfloat16* __restrict__ Bh, const __nv_bfloat16* __restrict__ Bl, int ldb,
    int K, u32 sb, float (*acc)[4][4]) {
    constexpr int MI = BM / TMW / 16;
    constexpr int NI = BN / TNW / 8;
    static_assert(NI == 4, "epilogue layout assumes NI==4");
    constexpr u32 OFF_AL = BM * 64;
    constexpr u32 OFF_BH = 2 * BM * 64;
    constexpr u32 OFF_BL = 2 * BM * 64 + BN * 64;
    constexpr u32 SS = (2 * BM + 2 * BN) * 64;   // bytes per stage (24576)
    const int tid = threadIdx.x;
    const int lane = tid & 31, wid = tid >> 5;
    const int wrow = (wid / TNW) * (BM / TMW);
    const int wcol = (wid % TNW) * (BN / TNW);
    const int NK = K >> 5;

    auto issue = [&](int kt) {
        const u32 st = sb + (u32)(kt % 3) * SS;
        const int k0 = kt << 5;
#pragma unroll
        for (int i = tid; i < BM * 4; i += 256) {
            int r = i >> 2, c = i & 3;
            u32 doff = (u32)(r * 64 + ((c ^ ((r >> 1) & 3)) << 4));
            cp16(st + doff, Ah + (size_t)r * lda + k0 + c * 8);
            cp16(st + OFF_AL + doff, Al + (size_t)r * lda + k0 + c * 8);
        }
#pragma unroll
        for (int i = tid; i < BN * 4; i += 256) {
            int r = i >> 2, c = i & 3;
            u32 doff = (u32)(r * 64 + ((c ^ ((r >> 1) & 3)) << 4));
            cp16(st + OFF_BH + doff, Bh + (size_t)r * ldb + k0 + c * 8);
            cp16(st + OFF_BL + doff, Bl + (size_t)r * ldb + k0 + c * 8);
        }
        cp_commit();
    };

    issue(0);
    if (NK > 1) issue(1);
    for (int kt = 0; kt < NK; kt++) {
        if (kt + 1 < NK) cp_wait<1>();     // oldest (kt) has landed
        else             cp_wait<0>();
        __syncthreads();                   // everyone done computing kt-1; kt data visible
        if (kt + 2 < NK) issue(kt + 2);    // overwrites buffer (kt+2)%3 == (kt-1)%3 (safe post-barrier)
        const u32 st = sb + (u32)(kt % 3) * SS;
#pragma unroll
        for (int ks = 0; ks < 2; ks++) {
            u32 ah[MI][4], al[MI][4], bh[NI][2], bl[NI][2];
            {
                const int kc = ks * 2 + (lane >> 4);
#pragma unroll
                for (int mi = 0; mi < MI; mi++) {
                    int r = wrow + mi * 16 + (lane & 15);
                    u32 a = st + (u32)(r * 64 + ((kc ^ ((r >> 1) & 3)) << 4));
                    ldm_x4(a, ah[mi][0], ah[mi][1], ah[mi][2], ah[mi][3]);
                    ldm_x4(a + OFF_AL, al[mi][0], al[mi][1], al[mi][2], al[mi][3]);
                }
            }
            {
                const int kc = ks * 2 + ((lane >> 3) & 1);
                const int rb = wcol + ((lane >> 4) << 3) + (lane & 7);
#pragma unroll
                for (int ni = 0; ni < NI; ni += 2) {
                    int r = rb + ni * 8;
                    u32 swz = (u32)(r * 64 + ((kc ^ ((r >> 1) & 3)) << 4));
                    ldm_x4(st + OFF_BH + swz, bh[ni][0], bh[ni][1], bh[ni + 1][0], bh[ni + 1][1]);
                    ldm_x4(st + OFF_BL + swz, bl[ni][0], bl[ni][1], bl[ni + 1][0], bl[ni + 1][1]);
                }
            }
#pragma unroll
            for (int mi = 0; mi < MI; mi++)
#pragma unroll
                for (int ni = 0; ni < NI; ni++) {
                    mma_bf16(acc[mi][ni], ah[mi], bh[ni]);   // hi*hi
                    mma_bf16(acc[mi][ni], ah[mi], bl[ni]);   // hi*lo
                    mma_bf16(acc[mi][ni], al[mi], bh[ni]);   // lo*hi
                }
        }
    }
}

#define GEMM_SMEM 73728   // 3 stages x 24576

// ============================ fp32 -> bf16 hi/lo split ============================
__global__ __launch_bounds__(256) void split_kernel(const float* __restrict__ in,
                                                    __nv_bfloat16* __restrict__ hi,
                                                    __nv_bfloat16* __restrict__ lo, int n) {
    int i = (blockIdx.x * 256 + threadIdx.x) * 4;
    if (i >= n) return;
    float4 v = *reinterpret_cast<const float4*>(in + i);
    u32 l0, l1;
    u32 h0 = pack_hi_lo(v.x, v.y, l0);
    u32 h1 = pack_hi_lo(v.z, v.w, l1);
    *reinterpret_cast<uint2*>(hi + i) = make_uint2(h0, h1);
    *reinterpret_cast<uint2*>(lo + i) = make_uint2(l0, l1);
}

// ============================ QKV GEMM + scatter ============================
__global__ __launch_bounds__(256) void qkv_mma() {
    extern __shared__ char smem[];
    u32 sb = smem_u32(smem);
    const int n0 = blockIdx.x * 64, m0 = blockIdx.y * 128;
    float acc[2][4][4];
#pragma unroll
    for (int i = 0; i < 2; i++)
#pragma unroll
        for (int j = 0; j < 4; j++)
#pragma unroll
            for (int k = 0; k < 4; k++) acc[i][j][k] = 0.f;
    gemm_core<128, 64, 4, 2>(g_xh + (size_t)m0 * CC, g_xl + (size_t)m0 * CC, CC,
                             g_wqh + (size_t)n0 * CC, g_wql + (size_t)n0 * CC, CC,
                             CC, sb, acc);
    const int tid = threadIdx.x, lane = tid & 31, wid = tid >> 5;
    const int wm = wid >> 1, wn = wid & 1;
#pragma unroll
    for (int mi = 0; mi < 2; mi++)
#pragma unroll
        for (int ni = 0; ni < 4; ni++) {
            int c = n0 + wn * 32 + ni * 8 + (lane & 3) * 2;
            int t = c / CC, rc = c - t * CC, h = rc >> 6, d0 = rc & 63;
            float sc = (t == 0) ? SCALE : 1.f;
            __nv_bfloat16* ph = (t == 0) ? g_qh : (t == 1) ? g_kh : g_vh;
            __nv_bfloat16* pl = (t == 0) ? g_ql : (t == 1) ? g_kl : g_vl;
#pragma unroll
            for (int hf = 0; hf < 2; hf++) {
                int m = m0 + wm * 32 + mi * 16 + (lane >> 2) + hf * 8;
                int b = m / NN, ntok = m - b * NN;
                size_t base = ((size_t)(b * HH + h) * NN + ntok) * HDIM + d0;
                u32 lw, hw = pack_hi_lo(acc[mi][ni][hf * 2] * sc, acc[mi][ni][hf * 2 + 1] * sc, lw);
                *reinterpret_cast<u32*>(ph + base) = hw;
                *reinterpret_cast<u32*>(pl + base) = lw;
            }
        }
}

// ============================ transpose V -> vT[d][n] ============================
__global__ __launch_bounds__(256) void transpose_v() {
    __shared__ __nv_bfloat16 th[32][33], tl[32][33];
    int n0 = blockIdx.x * 32, d0 = blockIdx.y * 32, bh = blockIdx.z;
    int tx = threadIdx.x, ty = threadIdx.y;
#pragma unroll
    for (int i = 0; i < 4; i++) {
        int n = n0 + ty + i * 8;
        size_t s = ((size_t)bh * NN + n) * HDIM + d0 + tx;
        th[ty + i * 8][tx] = g_vh[s];
        tl[ty + i * 8][tx] = g_vl[s];
    }
    __syncthreads();
#pragma unroll
    for (int i = 0; i < 4; i++) {
        int d = d0 + ty + i * 8;
        size_t t = ((size_t)bh * HDIM + d) * NN + n0 + tx;
        g_vth[t] = th[tx][ty + i * 8];
        g_vtl[t] = tl[tx][ty + i * 8];
    }
}

// ============================ score GEMM S = Q K^T per (b,h) ============================
__global__ __launch_bounds__(256) void score_mma() {
    extern __shared__ char smem[];
    u32 sb = smem_u32(smem);
    const int n0 = blockIdx.x * 64, m0 = blockIdx.y * 128, bh = blockIdx.z;
    float acc[2][4][4];
#pragma unroll
    for (int i = 0; i < 2; i++)
#pragma unroll
        for (int j = 0; j < 4; j++)
#pragma unroll
            for (int k = 0; k < 4; k++) acc[i][j][k] = 0.f;
    const size_t ab = ((size_t)bh * NN + m0) * HDIM;
    const size_t bb = ((size_t)bh * NN + n0) * HDIM;
    gemm_core<128, 64, 4, 2>(g_qh + ab, g_ql + ab, HDIM,
                             g_kh + bb, g_kl + bb, HDIM, HDIM, sb, acc);
    const int tid = threadIdx.x, lane = tid & 31, wid = tid >> 5;
    const int wm = wid >> 1, wn = wid & 1;
    float* outb = g_attn + (size_t)bh * NN * NN;
#pragma unroll
    for (int mi = 0; mi < 2; mi++)
#pragma unroll
        for (int ni = 0; ni < 4; ni++) {
            int c = n0 + wn * 32 + ni * 8 + (lane & 3) * 2;
#pragma unroll
            for (int hf = 0; hf < 2; hf++) {
                int m = m0 + wm * 32 + mi * 16 + (lane >> 2) + hf * 8;
                if (m < NN)
                    *reinterpret_cast<float2*>(outb + (size_t)m * NN + c) =
                        make_float2(acc[mi][ni][hf * 2], acc[mi][ni][hf * 2 + 1]);
            }
        }
}

// ============================ softmax + both talking-heads mixes ============================
__global__ __launch_bounds__(384) void softmax_mix_kernel(const float* __restrict__ Wl,
                                                          const float* __restrict__ bl,
                                                          const float* __restrict__ Ww,
                                                          const float* __restrict__ bw) {
    __shared__ __align__(16) float sm[HH][NN];
    __shared__ float wls[HH * HH], bls[HH], wws[HH * HH], bws[HH];
    const int bm = blockIdx.x;
    const int b = bm / NN, m = bm % NN;
    const int tid = threadIdx.x, lane = tid & 31, wid = tid >> 5;

    if (tid < HH * HH) { wls[tid] = Wl[tid]; wws[tid] = Ww[tid]; }
    if (tid < HH) { bls[tid] = bl[tid]; bws[tid] = bw[tid]; }

    // vectorized load: 12 head-rows of this token row
    for (int idx = tid; idx < HH * NN / 4; idx += 384) {
        int h = idx / (NN / 4), n4 = idx - h * (NN / 4);
        float4 v = *reinterpret_cast<const float4*>(
            &g_attn[((size_t)(b * HH + h) * NN + m) * NN + n4 * 4]);
        *reinterpret_cast<float4*>(&sm[h][n4 * 4]) = v;
    }
    __syncthreads();

    for (int n = tid; n < NN; n += 384) {
        float p[HH];
#pragma unroll
        for (int h = 0; h < HH; h++) p[h] = sm[h][n];
#pragma unroll
        for (int g = 0; g < HH; g++) {
            float o = bls[g];
#pragma unroll
            for (int h = 0; h < HH; h++) o += wls[g * HH + h] * p[h];
            sm[g][n] = o;
        }
    }
    __syncthreads();

    {
        const int h = wid;
        float mx = -1e30f;
        for (int n = lane; n < NN; n += 32) mx = fmaxf(mx, sm[h][n]);
#pragma unroll
        for (int o = 16; o > 0; o >>= 1) mx = fmaxf(mx, __shfl_xor_sync(0xffffffffu, mx, o));
        float sum = 0.f;
        for (int n = lane; n < NN; n += 32) {
            float e = __expf(sm[h][n] - mx);
            sm[h][n] = e; sum += e;
        }
#pragma unroll
        for (int o = 16; o > 0; o >>= 1) sum += __shfl_xor_sync(0xffffffffu, sum, o);
        float inv = 1.f / sum;
        for (int n = lane; n < NN; n += 32) sm[h][n] *= inv;
    }
    __syncthreads();

    for (int n2 = tid; n2 < NN / 2; n2 += 384) {
        int n = n2 * 2;
        float p0[HH], p1[HH];
#pragma unroll
        for (int h = 0; h < HH; h++) { p0[h] = sm[h][n]; p1[h] = sm[h][n + 1]; }
#pragma unroll
        for (int g = 0; g < HH; g++) {
            float o0 = bws[g], o1 = bws[g];
#pragma unroll
            for (int h = 0; h < HH; h++) { o0 += wws[g * HH + h] * p0[h]; o1 += wws[g * HH + h] * p1[h]; }
            size_t idx = ((size_t)(b * HH + g) * NN + m) * NN + n;
            u32 lw, hw = pack_hi_lo(o0, o1, lw);
            *reinterpret_cast<u32*>(g_a2h + idx) = hw;
            *reinterpret_cast<u32*>(g_a2l + idx) = lw;
        }
    }
}

// ============================ O = attn2 @ V per (b,h) ============================
__global__ __launch_bounds__(256) void av_mma() {
    extern __shared__ char smem[];
    u32 sb = smem_u32(smem);
    const int m0 = blockIdx.x * 128, bh = blockIdx.y;
    float acc[2][4][4];
#pragma unroll
    for (int i = 0; i < 2; i++)
#pragma unroll
        for (int j = 0; j < 4; j++)
#pragma unroll
            for (int k = 0; k < 4; k++) acc[i][j][k] = 0.f;
    const size_t ab = (size_t)bh * NN * NN + (size_t)m0 * NN;
    const size_t bb = (size_t)bh * HDIM * NN;
    gemm_core<128, 64, 4, 2>(g_a2h + ab, g_a2l + ab, NN,
                             g_vth + bb, g_vtl + bb, NN, NN, sb, acc);
    const int tid = threadIdx.x, lane = tid & 31, wid = tid >> 5;
    const int wm = wid >> 1, wn = wid & 1;
    const int b = bh / HH, h = bh - b * HH;
#pragma unroll
    for (int mi = 0; mi < 2; mi++)
#pragma unroll
        for (int ni = 0; ni < 4; ni++) {
            int dc = wn * 32 + ni * 8 + (lane & 3) * 2;
#pragma unroll
            for (int hf = 0; hf < 2; hf++) {
                int m = m0 + wm * 32 + mi * 16 + (lane >> 2) + hf * 8;
                if (m < NN) {
                    size_t base = ((size_t)b * NN + m) * CC + h * HDIM + dc;
                    u32 lw, hw = pack_hi_lo(acc[mi][ni][hf * 2], acc[mi][ni][hf * 2 + 1], lw);
                    *reinterpret_cast<u32*>(g_o1h + base) = hw;
                    *reinterpret_cast<u32*>(g_o1l + base) = lw;
                }
            }
        }
}

// ============================ out = o1 @ Wproj^T + bias ============================
__global__ __launch_bounds__(256) void proj_mma(const float* __restrict__ bias,
                                                float* __restrict__ out) {
    extern __shared__ char smem[];
    u32 sb = smem_u32(smem);
    const int n0 = blockIdx.x * 64, m0 = blockIdx.y * 128;
    float acc[2][4][4];
#pragma unroll
    for (int i = 0; i < 2; i++)
#pragma unroll
        for (int j = 0; j < 4; j++)
#pragma unroll
            for (int k = 0; k < 4; k++) acc[i][j][k] = 0.f;
    gemm_core<128, 64, 4, 2>(g_o1h + (size_t)m0 * CC, g_o1l + (size_t)m0 * CC, CC,
                             g_wph + (size_t)n0 * CC, g_wpl + (size_t)n0 * CC, CC,
                             CC, sb, acc);
    const int tid = threadIdx.x, lane = tid & 31, wid = tid >> 5;
    const int wm = wid >> 1, wn = wid & 1;
#pragma unroll
    for (int mi = 0; mi < 2; mi++)
#pragma unroll
        for (int ni = 0; ni < 4; ni++) {
            int c = n0 + wn * 32 + ni * 8 + (lane & 3) * 2;
            float b0 = __ldg(&bias[c]), b1 = __ldg(&bias[c + 1]);
#pragma unroll
            for (int hf = 0; hf < 2; hf++) {
                int m = m0 + wm * 32 + mi * 16 + (lane >> 2) + hf * 8;
                *reinterpret_cast<float2*>(out + (size_t)m * CC + c) =
                    make_float2(acc[mi][ni][hf * 2] + b0, acc[mi][ni][hf * 2 + 1] + b1);
            }
        }
}

// ============================ launch ============================
extern "C" void kernel_launch(void* const* d_in, const int* in_sizes, int n_in,
                              void* d_out, int out_size) {
    const float* x     = (const float*)d_in[0];
    const float* Wqkv  = (const float*)d_in[1];
    const float* Wl    = (const float*)d_in[2];
    const float* bl    = (const float*)d_in[3];
    const float* Ww    = (const float*)d_in[4];
    const float* bw    = (const float*)d_in[5];
    const float* Wproj = (const float*)d_in[6];
    const float* bproj = (const float*)d_in[7];
    float* out = (float*)d_out;

    static bool attr_done = false;
    if (!attr_done) {
        cudaFuncSetAttribute(qkv_mma,   cudaFuncAttributeMaxDynamicSharedMemorySize, GEMM_SMEM);
        cudaFuncSetAttribute(score_mma, cudaFuncAttributeMaxDynamicSharedMemorySize, GEMM_SMEM);
        cudaFuncSetAttribute(av_mma,    cudaFuncAttributeMaxDynamicSharedMemorySize, GEMM_SMEM);
        cudaFuncSetAttribute(proj_mma,  cudaFuncAttributeMaxDynamicSharedMemorySize, GEMM_SMEM);
        attr_done = true;
    }

    __nv_bfloat16 *xh, *xl, *wqh, *wql, *wph, *wpl;
    cudaGetSymbolAddress((void**)&xh, g_xh);   cudaGetSymbolAddress((void**)&xl, g_xl);
    cudaGetSymbolAddress((void**)&wqh, g_wqh); cudaGetSymbolAddress((void**)&wql, g_wql);
    cudaGetSymbolAddress((void**)&wph, g_wph); cudaGetSymbolAddress((void**)&wpl, g_wpl);

    split_kernel<<<(MTOT * CC / 4 + 255) / 256, 256>>>(x, xh, xl, MTOT * CC);
    split_kernel<<<(3 * CC * CC / 4 + 255) / 256, 256>>>(Wqkv, wqh, wql, 3 * CC * CC);
    split_kernel<<<(CC * CC / 4 + 255) / 256, 256>>>(Wproj, wph, wpl, CC * CC);

    qkv_mma<<<dim3(36, 72), 256, GEMM_SMEM>>>();
    transpose_v<<<dim3(18, 2, BB * HH), dim3(32, 8)>>>();
    score_mma<<<dim3(9, 5, BB * HH), 256, GEMM_SMEM>>>();
    softmax_mix_kernel<<<MTOT, 384>>>(Wl, bl, Ww, bw);
    av_mma<<<dim3(5, BB * HH), 256, GEMM_SMEM>>>();
    proj_mma<<<dim3(12, 72), 256, GEMM_SMEM>>>(bproj, out);
}

// round 7
// speedup vs baseline: 2.5856x; 1.0098x over previous
#include <cuda_runtime.h>
#include <cuda_bf16.h>

// Talking-heads attention via mma.sync bf16 tensor cores (plain sm_100 ISA).
// All GEMMs: bf16 hi/lo split (3 MMAs) -> fp32-class accuracy, fp32 accumulators.
// v7: BN=128 tiles for qkv/proj; score rewritten as persistent-Q n-loop kernel.

#define BB 16
#define NN 576
#define CC 768
#define HH 12
#define HDIM 64
#define MTOT (BB * NN)
#define SCALE 0.125f
#define ATT ((size_t)BB * HH * NN * NN)
#define QKE (BB * HH * NN * HDIM)

typedef unsigned int u32;

// ============================ PTX helpers (sm_80+ ISA only) ============================
__device__ __forceinline__ u32 smem_u32(const void* p) {
    u32 a;
    asm("{ .reg .u64 t; cvta.to.shared.u64 t, %1; cvt.u32.u64 %0, t; }" : "=r"(a) : "l"(p));
    return a;
}
__device__ __forceinline__ void cp16(u32 dst, const void* src) {
    asm volatile("cp.async.cg.shared.global [%0], [%1], 16;" :: "r"(dst), "l"(src));
}
__device__ __forceinline__ void cp_commit() {
    asm volatile("cp.async.commit_group;" ::: "memory");
}
template <int N>
__device__ __forceinline__ void cp_wait() {
    asm volatile("cp.async.wait_group %0;" :: "n"(N) : "memory");
}
__device__ __forceinline__ void ldm_x4(u32 a, u32& r0, u32& r1, u32& r2, u32& r3) {
    asm volatile("ldmatrix.sync.aligned.m8n8.x4.shared.b16 {%0,%1,%2,%3}, [%4];"
                 : "=r"(r0), "=r"(r1), "=r"(r2), "=r"(r3) : "r"(a));
}
__device__ __forceinline__ void mma_bf16(float* d, const u32* a, const u32* b) {
    asm volatile("mma.sync.aligned.m16n8k16.row.col.f32.bf16.bf16.f32 "
                 "{%0,%1,%2,%3}, {%4,%5,%6,%7}, {%8,%9}, {%0,%1,%2,%3};"
                 : "+f"(d[0]), "+f"(d[1]), "+f"(d[2]), "+f"(d[3])
                 : "r"(a[0]), "r"(a[1]), "r"(a[2]), "r"(a[3]), "r"(b[0]), "r"(b[1]));
}

// ============================ scratch (16B-aligned) ============================
__device__ __align__(16) __nv_bfloat16 g_xh[MTOT * CC], g_xl[MTOT * CC];
__device__ __align__(16) __nv_bfloat16 g_wqh[3 * CC * CC], g_wql[3 * CC * CC];
__device__ __align__(16) __nv_bfloat16 g_wph[CC * CC], g_wpl[CC * CC];
__device__ __align__(16) __nv_bfloat16 g_qh[QKE + 64 * HDIM], g_ql[QKE + 64 * HDIM];
__device__ __align__(16) __nv_bfloat16 g_kh[QKE + 64 * HDIM], g_kl[QKE + 64 * HDIM];
__device__ __align__(16) __nv_bfloat16 g_vh[QKE], g_vl[QKE];
__device__ __align__(16) __nv_bfloat16 g_vth[QKE], g_vtl[QKE];
__device__ __align__(16) float g_attn[ATT];
__device__ __align__(16) __nv_bfloat16 g_a2h[ATT + 64 * NN], g_a2l[ATT + 64 * NN];
__device__ __align__(16) __nv_bfloat16 g_o1h[MTOT * CC], g_o1l[MTOT * CC];

__device__ __forceinline__ u32 pack_hi_lo(float f0, float f1, u32& lo_out) {
    __nv_bfloat16 h0 = __float2bfloat16(f0);
    __nv_bfloat16 h1 = __float2bfloat16(f1);
    __nv_bfloat16 l0 = __float2bfloat16(f0 - __bfloat162float(h0));
    __nv_bfloat16 l1 = __float2bfloat16(f1 - __bfloat162float(h1));
    u32 hw = ((u32)__bfloat16_as_ushort(h1) << 16) | __bfloat16_as_ushort(h0);
    lo_out = ((u32)__bfloat16_as_ushort(l1) << 16) | __bfloat16_as_ushort(l0);
    return hw;
}

// ============================ core GEMM mainloop (3-stage pipeline) ============================
// C[m,n] = sum_k A[m,k]*B[n,k]; BM x BN tile, BK=32, 256 threads, TMW x TNW warps.
// Per-mi A-fragment loads keep live registers low for the BN=128 instantiation.
template <int BM, int BN, int TMW, int TNW>
__device__ __forceinline__ void gemm_core(
    const __nv_bfloat16* __restrict__ Ah, const __nv_bfloat16* __restrict__ Al, int lda,
    const __nv_bfloat16* __restrict__ Bh, const __nv_bfloat16* __restrict__ Bl, int ldb,
    int K, u32 sb, float (*acc)[4][4]) {
    constexpr int MI = BM / TMW / 16;
    constexpr int NI = BN / TNW / 8;
    static_assert(NI == 4, "epilogue layout assumes NI==4");
    constexpr u32 OFF_AL = BM * 64;
    constexpr u32 OFF_BH = 2 * BM * 64;
    constexpr u32 OFF_BL = 2 * BM * 64 + BN * 64;
    constexpr u32 SS = (2 * BM + 2 * BN) * 64;
    const int tid = threadIdx.x;
    const int lane = tid & 31, wid = tid >> 5;
    const int wrow = (wid / TNW) * (BM / TMW);
    const int wcol = (wid % TNW) * (BN / TNW);
    const int NK = K >> 5;

    auto issue = [&](int kt) {
        const u32 st = sb + (u32)(kt % 3) * SS;
        const int k0 = kt << 5;
#pragma unroll
        for (int i = tid; i < BM * 4; i += 256) {
            int r = i >> 2, c = i & 3;
            u32 doff = (u32)(r * 64 + ((c ^ ((r >> 1) & 3)) << 4));
            cp16(st + doff, Ah + (size_t)r * lda + k0 + c * 8);
            cp16(st + OFF_AL + doff, Al + (size_t)r * lda + k0 + c * 8);
        }
#pragma unroll
        for (int i = tid; i < BN * 4; i += 256) {
            int r = i >> 2, c = i & 3;
            u32 doff = (u32)(r * 64 + ((c ^ ((r >> 1) & 3)) << 4));
            cp16(st + OFF_BH + doff, Bh + (size_t)r * ldb + k0 + c * 8);
            cp16(st + OFF_BL + doff, Bl + (size_t)r * ldb + k0 + c * 8);
        }
        cp_commit();
    };

    issue(0);
    if (NK > 1) issue(1);
    for (int kt = 0; kt < NK; kt++) {
        if (kt + 1 < NK) cp_wait<1>();
        else             cp_wait<0>();
        __syncthreads();
        if (kt + 2 < NK) issue(kt + 2);
        const u32 st = sb + (u32)(kt % 3) * SS;
#pragma unroll
        for (int ks = 0; ks < 2; ks++) {
            u32 bhf[NI][2], blf[NI][2];
            {
                const int kc = ks * 2 + ((lane >> 3) & 1);
                const int rb = wcol + ((lane >> 4) << 3) + (lane & 7);
#pragma unroll
                for (int ni = 0; ni < NI; ni += 2) {
                    int r = rb + ni * 8;
                    u32 swz = (u32)(r * 64 + ((kc ^ ((r >> 1) & 3)) << 4));
                    ldm_x4(st + OFF_BH + swz, bhf[ni][0], bhf[ni][1], bhf[ni + 1][0], bhf[ni + 1][1]);
                    ldm_x4(st + OFF_BL + swz, blf[ni][0], blf[ni][1], blf[ni + 1][0], blf[ni + 1][1]);
                }
            }
            const int kcA = ks * 2 + (lane >> 4);
#pragma unroll
            for (int mi = 0; mi < MI; mi++) {
                int r = wrow + mi * 16 + (lane & 15);
                u32 a = st + (u32)(r * 64 + ((kcA ^ ((r >> 1) & 3)) << 4));
                u32 ahf[4], alf[4];
                ldm_x4(a, ahf[0], ahf[1], ahf[2], ahf[3]);
                ldm_x4(a + OFF_AL, alf[0], alf[1], alf[2], alf[3]);
#pragma unroll
                for (int ni = 0; ni < NI; ni++) {
                    mma_bf16(acc[mi][ni], ahf, bhf[ni]);   // hi*hi
                    mma_bf16(acc[mi][ni], ahf, blf[ni]);   // hi*lo
                    mma_bf16(acc[mi][ni], alf, bhf[ni]);   // lo*hi
                }
            }
        }
    }
}

#define GEMM_SMEM_BIG 98304   // 3 stages x 32768 (BM=128,BN=128)
#define GEMM_SMEM_AV  73728   // 3 stages x 24576 (BM=128,BN=64)
#define SCORE_SMEM    81920   // A 32768 + 3 stages x 16384

// ============================ fp32 -> bf16 hi/lo split ============================
__global__ __launch_bounds__(256) void split_kernel(const float* __restrict__ in,
                                                    __nv_bfloat16* __restrict__ hi,
                                                    __nv_bfloat16* __restrict__ lo, int n) {
    int i = (blockIdx.x * 256 + threadIdx.x) * 4;
    if (i >= n) return;
    float4 v = *reinterpret_cast<const float4*>(in + i);
    u32 l0, l1;
    u32 h0 = pack_hi_lo(v.x, v.y, l0);
    u32 h1 = pack_hi_lo(v.z, v.w, l1);
    *reinterpret_cast<uint2*>(hi + i) = make_uint2(h0, h1);
    *reinterpret_cast<uint2*>(lo + i) = make_uint2(l0, l1);
}

// ============================ QKV GEMM + scatter (BN=128) ============================
// grid (2304/128=18, 9216/128=72)
__global__ __launch_bounds__(256, 2) void qkv_mma() {
    extern __shared__ char smem[];
    u32 sb = smem_u32(smem);
    const int n0 = blockIdx.x * 128, m0 = blockIdx.y * 128;
    float acc[4][4][4];
#pragma unroll
    for (int i = 0; i < 4; i++)
#pragma unroll
        for (int j = 0; j < 4; j++)
#pragma unroll
            for (int k = 0; k < 4; k++) acc[i][j][k] = 0.f;
    gemm_core<128, 128, 2, 4>(g_xh + (size_t)m0 * CC, g_xl + (size_t)m0 * CC, CC,
                              g_wqh + (size_t)n0 * CC, g_wql + (size_t)n0 * CC, CC,
                              CC, sb, acc);
    const int tid = threadIdx.x, lane = tid & 31, wid = tid >> 5;
    const int wm = wid >> 2, wn = wid & 3;
#pragma unroll
    for (int mi = 0; mi < 4; mi++)
#pragma unroll
        for (int ni = 0; ni < 4; ni++) {
            int c = n0 + wn * 32 + ni * 8 + (lane & 3) * 2;
            int t = c / CC, rc = c - t * CC, h = rc >> 6, d0 = rc & 63;
            float sc = (t == 0) ? SCALE : 1.f;
            __nv_bfloat16* ph = (t == 0) ? g_qh : (t == 1) ? g_kh : g_vh;
            __nv_bfloat16* pl = (t == 0) ? g_ql : (t == 1) ? g_kl : g_vl;
#pragma unroll
            for (int hf = 0; hf < 2; hf++) {
                int m = m0 + wm * 64 + mi * 16 + (lane >> 2) + hf * 8;
                int b = m / NN, ntok = m - b * NN;
                size_t base = ((size_t)(b * HH + h) * NN + ntok) * HDIM + d0;
                u32 lw, hw = pack_hi_lo(acc[mi][ni][hf * 2] * sc, acc[mi][ni][hf * 2 + 1] * sc, lw);
                *reinterpret_cast<u32*>(ph + base) = hw;
                *reinterpret_cast<u32*>(pl + base) = lw;
            }
        }
}

// ============================ transpose V -> vT[d][n] ============================
__global__ __launch_bounds__(256) void transpose_v() {
    __shared__ __nv_bfloat16 th[32][33], tl[32][33];
    int n0 = blockIdx.x * 32, d0 = blockIdx.y * 32, bh = blockIdx.z;
    int tx = threadIdx.x, ty = threadIdx.y;
#pragma unroll
    for (int i = 0; i < 4; i++) {
        int n = n0 + ty + i * 8;
        size_t s = ((size_t)bh * NN + n) * HDIM + d0 + tx;
        th[ty + i * 8][tx] = g_vh[s];
        tl[ty + i * 8][tx] = g_vl[s];
    }
    __syncthreads();
#pragma unroll
    for (int i = 0; i < 4; i++) {
        int d = d0 + ty + i * 8;
        size_t t = ((size_t)bh * HDIM + d) * NN + n0 + tx;
        g_vth[t] = th[tx][ty + i * 8];
        g_vtl[t] = tl[tx][ty + i * 8];
    }
}

// ============================ score: persistent-Q n-loop kernel ============================
// grid (5, 192). CTA: Q tile (128 x 64, hi/lo) resident; K tiles (64 x 64) stream
// through a 3-stage cp.async ring across 9 n-tiles. S written fp32.
__global__ __launch_bounds__(256) void score_mma() {
    extern __shared__ char smem[];
    u32 sb = smem_u32(smem);
    const u32 A_HI = 0, A_LO = 16384, RING = 32768;   // B stage: BH 8192 + BL 8192
    const int m0 = blockIdx.x * 128, bhi = blockIdx.y;
    const int tid = threadIdx.x, lane = tid & 31, wid = tid >> 5;
    const int wm = wid >> 1, wn = wid & 1;
    const int wrow = wm * 32, wcol = wn * 32;

    const __nv_bfloat16* Qh = g_qh + ((size_t)bhi * NN + m0) * HDIM;
    const __nv_bfloat16* Ql = g_ql + ((size_t)bhi * NN + m0) * HDIM;
    const __nv_bfloat16* Kh = g_kh + (size_t)bhi * NN * HDIM;
    const __nv_bfloat16* Kl = g_kl + (size_t)bhi * NN * HDIM;

    // Q tile (both k-subtiles), loaded once. Rows m0+r beyond 576 hit the pad.
#pragma unroll
    for (int i = tid; i < 128 * 8; i += 256) {
        int r = i >> 3, cc = i & 7, kt = cc >> 2, c = cc & 3;
        u32 doff = (u32)(kt * 8192 + r * 64 + ((c ^ ((r >> 1) & 3)) << 4));
        size_t so = (size_t)r * HDIM + kt * 32 + c * 8;
        cp16(sb + A_HI + doff, Qh + so);
        cp16(sb + A_LO + doff, Ql + so);
    }
    cp_commit();

    auto issueB = [&](int nt) {
        const u32 st = sb + RING + (u32)(nt % 3) * 16384;
#pragma unroll
        for (int i = tid; i < 64 * 8; i += 256) {
            int r = i >> 3, cc = i & 7, kt = cc >> 2, c = cc & 3;
            u32 doff = (u32)(kt * 4096 + r * 64 + ((c ^ ((r >> 1) & 3)) << 4));
            size_t so = (size_t)(nt * 64 + r) * HDIM + kt * 32 + c * 8;
            cp16(st + doff, Kh + so);
            cp16(st + 8192 + doff, Kl + so);
        }
        cp_commit();
    };
    issueB(0); issueB(1);

    float* outb = g_attn + (size_t)bhi * NN * NN;
    for (int nt = 0; nt < 9; nt++) {
        if (nt < 8) cp_wait<1>();
        else        cp_wait<0>();
        __syncthreads();
        if (nt + 2 < 9) issueB(nt + 2);
        const u32 st = sb + RING + (u32)(nt % 3) * 16384;

        float acc[2][4][4];
#pragma unroll
        for (int i = 0; i < 2; i++)
#pragma unroll
            for (int j = 0; j < 4; j++)
#pragma unroll
                for (int k = 0; k < 4; k++) acc[i][j][k] = 0.f;

#pragma unroll
        for (int kt = 0; kt < 2; kt++)
#pragma unroll
            for (int ks = 0; ks < 2; ks++) {
                u32 bhf[4][2], blf[4][2];
                {
                    const int kc = ks * 2 + ((lane >> 3) & 1);
                    const int rb = wcol + ((lane >> 4) << 3) + (lane & 7);
#pragma unroll
                    for (int ni = 0; ni < 4; ni += 2) {
                        int r = rb + ni * 8;
                        u32 swz = (u32)(kt * 4096 + r * 64 + ((kc ^ ((r >> 1) & 3)) << 4));
                        ldm_x4(st + swz, bhf[ni][0], bhf[ni][1], bhf[ni + 1][0], bhf[ni + 1][1]);
                        ldm_x4(st + 8192 + swz, blf[ni][0], blf[ni][1], blf[ni + 1][0], blf[ni + 1][1]);
                    }
                }
                const int kcA = ks * 2 + (lane >> 4);
#pragma unroll
                for (int mi = 0; mi < 2; mi++) {
                    int r = wrow + mi * 16 + (lane & 15);
                    u32 aoff = (u32)(kt * 8192 + r * 64 + ((kcA ^ ((r >> 1) & 3)) << 4));
                    u32 ahf[4], alf[4];
                    ldm_x4(sb + A_HI + aoff, ahf[0], ahf[1], ahf[2], ahf[3]);
                    ldm_x4(sb + A_LO + aoff, alf[0], alf[1], alf[2], alf[3]);
#pragma unroll
                    for (int ni = 0; ni < 4; ni++) {
                        mma_bf16(acc[mi][ni], ahf, bhf[ni]);
                        mma_bf16(acc[mi][ni], ahf, blf[ni]);
                        mma_bf16(acc[mi][ni], alf, bhf[ni]);
                    }
                }
            }

        const int n0 = nt * 64;
#pragma unroll
        for (int mi = 0; mi < 2; mi++)
#pragma unroll
            for (int ni = 0; ni < 4; ni++) {
                int c = n0 + wn * 32 + ni * 8 + (lane & 3) * 2;
#pragma unroll
                for (int hf = 0; hf < 2; hf++) {
                    int m = m0 + wm * 32 + mi * 16 + (lane >> 2) + hf * 8;
                    if (m < NN)
                        *reinterpret_cast<float2*>(outb + (size_t)m * NN + c) =
                            make_float2(acc[mi][ni][hf * 2], acc[mi][ni][hf * 2 + 1]);
                }
            }
    }
}

// ============================ softmax + both talking-heads mixes ============================
__global__ __launch_bounds__(384) void softmax_mix_kernel(const float* __restrict__ Wl,
                                                          const float* __restrict__ bl,
                                                          const float* __restrict__ Ww,
                                                          const float* __restrict__ bw) {
    __shared__ __align__(16) float sm[HH][NN];
    __shared__ float wls[HH * HH], bls[HH], wws[HH * HH], bws[HH];
    const int bm = blockIdx.x;
    const int b = bm / NN, m = bm % NN;
    const int tid = threadIdx.x, lane = tid & 31, wid = tid >> 5;

    if (tid < HH * HH) { wls[tid] = Wl[tid]; wws[tid] = Ww[tid]; }
    if (tid < HH) { bls[tid] = bl[tid]; bws[tid] = bw[tid]; }

    for (int idx = tid; idx < HH * NN / 4; idx += 384) {
        int h = idx / (NN / 4), n4 = idx - h * (NN / 4);
        float4 v = *reinterpret_cast<const float4*>(
            &g_attn[((size_t)(b * HH + h) * NN + m) * NN + n4 * 4]);
        *reinterpret_cast<float4*>(&sm[h][n4 * 4]) = v;
    }
    __syncthreads();

    for (int n = tid; n < NN; n += 384) {
        float p[HH];
#pragma unroll
        for (int h = 0; h < HH; h++) p[h] = sm[h][n];
#pragma unroll
        for (int g = 0; g < HH; g++) {
            float o = bls[g];
#pragma unroll
            for (int h = 0; h < HH; h++) o += wls[g * HH + h] * p[h];
            sm[g][n] = o;
        }
    }
    __syncthreads();

    {
        const int h = wid;
        float mx = -1e30f;
        for (int n = lane; n < NN; n += 32) mx = fmaxf(mx, sm[h][n]);
#pragma unroll
        for (int o = 16; o > 0; o >>= 1) mx = fmaxf(mx, __shfl_xor_sync(0xffffffffu, mx, o));
        float sum = 0.f;
        for (int n = lane; n < NN; n += 32) {
            float e = __expf(sm[h][n] - mx);
            sm[h][n] = e; sum += e;
        }
#pragma unroll
        for (int o = 16; o > 0; o >>= 1) sum += __shfl_xor_sync(0xffffffffu, sum, o);
        float inv = 1.f / sum;
        for (int n = lane; n < NN; n += 32) sm[h][n] *= inv;
    }
    __syncthreads();

    for (int n2 = tid; n2 < NN / 2; n2 += 384) {
        int n = n2 * 2;
        float p0[HH], p1[HH];
#pragma unroll
        for (int h = 0; h < HH; h++) { p0[h] = sm[h][n]; p1[h] = sm[h][n + 1]; }
#pragma unroll
        for (int g = 0; g < HH; g++) {
            float o0 = bws[g], o1 = bws[g];
#pragma unroll
            for (int h = 0; h < HH; h++) { o0 += wws[g * HH + h] * p0[h]; o1 += wws[g * HH + h] * p1[h]; }
            size_t idx = ((size_t)(b * HH + g) * NN + m) * NN + n;
            u32 lw, hw = pack_hi_lo(o0, o1, lw);
            *reinterpret_cast<u32*>(g_a2h + idx) = hw;
            *reinterpret_cast<u32*>(g_a2l + idx) = lw;
        }
    }
}

// ============================ O = attn2 @ V per (b,h) ============================
// grid (5, 192). K = 576.
__global__ __launch_bounds__(256) void av_mma() {
    extern __shared__ char smem[];
    u32 sb = smem_u32(smem);
    const int m0 = blockIdx.x * 128, bh = blockIdx.y;
    float acc[2][4][4];
#pragma unroll
    for (int i = 0; i < 2; i++)
#pragma unroll
        for (int j = 0; j < 4; j++)
#pragma unroll
            for (int k = 0; k < 4; k++) acc[i][j][k] = 0.f;
    const size_t ab = (size_t)bh * NN * NN + (size_t)m0 * NN;
    const size_t bb = (size_t)bh * HDIM * NN;
    gemm_core<128, 64, 4, 2>(g_a2h + ab, g_a2l + ab, NN,
                             g_vth + bb, g_vtl + bb, NN, NN, sb, acc);
    const int tid = threadIdx.x, lane = tid & 31, wid = tid >> 5;
    const int wm = wid >> 1, wn = wid & 1;
    const int b = bh / HH, h = bh - b * HH;
#pragma unroll
    for (int mi = 0; mi < 2; mi++)
#pragma unroll
        for (int ni = 0; ni < 4; ni++) {
            int dc = wn * 32 + ni * 8 + (lane & 3) * 2;
#pragma unroll
            for (int hf = 0; hf < 2; hf++) {
                int m = m0 + wm * 32 + mi * 16 + (lane >> 2) + hf * 8;
                if (m < NN) {
                    size_t base = ((size_t)b * NN + m) * CC + h * HDIM + dc;
                    u32 lw, hw = pack_hi_lo(acc[mi][ni][hf * 2], acc[mi][ni][hf * 2 + 1], lw);
                    *reinterpret_cast<u32*>(g_o1h + base) = hw;
                    *reinterpret_cast<u32*>(g_o1l + base) = lw;
                }
            }
        }
}

// ============================ out = o1 @ Wproj^T + bias (BN=128) ============================
// grid (6, 72)
__global__ __launch_bounds__(256, 2) void proj_mma(const float* __restrict__ bias,
                                                   float* __restrict__ out) {
    extern __shared__ char smem[];
    u32 sb = smem_u32(smem);
    const int n0 = blockIdx.x * 128, m0 = blockIdx.y * 128;
    float acc[4][4][4];
#pragma unroll
    for (int i = 0; i < 4; i++)
#pragma unroll
        for (int j = 0; j < 4; j++)
#pragma unroll
            for (int k = 0; k < 4; k++) acc[i][j][k] = 0.f;
    gemm_core<128, 128, 2, 4>(g_o1h + (size_t)m0 * CC, g_o1l + (size_t)m0 * CC, CC,
                              g_wph + (size_t)n0 * CC, g_wpl + (size_t)n0 * CC, CC,
                              CC, sb, acc);
    const int tid = threadIdx.x, lane = tid & 31, wid = tid >> 5;
    const int wm = wid >> 2, wn = wid & 3;
#pragma unroll
    for (int mi = 0; mi < 4; mi++)
#pragma unroll
        for (int ni = 0; ni < 4; ni++) {
            int c = n0 + wn * 32 + ni * 8 + (lane & 3) * 2;
            float b0 = __ldg(&bias[c]), b1 = __ldg(&bias[c + 1]);
#pragma unroll
            for (int hf = 0; hf < 2; hf++) {
                int m = m0 + wm * 64 + mi * 16 + (lane >> 2) + hf * 8;
                *reinterpret_cast<float2*>(out + (size_t)m * CC + c) =
                    make_float2(acc[mi][ni][hf * 2] + b0, acc[mi][ni][hf * 2 + 1] + b1);
            }
        }
}

// ============================ launch ============================
extern "C" void kernel_launch(void* const* d_in, const int* in_sizes, int n_in,
                              void* d_out, int out_size) {
    const float* x     = (const float*)d_in[0];
    const float* Wqkv  = (const float*)d_in[1];
    const float* Wl    = (const float*)d_in[2];
    const float* bl    = (const float*)d_in[3];
    const float* Ww    = (const float*)d_in[4];
    const float* bw    = (const float*)d_in[5];
    const float* Wproj = (const float*)d_in[6];
    const float* bproj = (const float*)d_in[7];
    float* out = (float*)d_out;

    static bool attr_done = false;
    if (!attr_done) {
        cudaFuncSetAttribute(qkv_mma,   cudaFuncAttributeMaxDynamicSharedMemorySize, GEMM_SMEM_BIG);
        cudaFuncSetAttribute(score_mma, cudaFuncAttributeMaxDynamicSharedMemorySize, SCORE_SMEM);
        cudaFuncSetAttribute(av_mma,    cudaFuncAttributeMaxDynamicSharedMemorySize, GEMM_SMEM_AV);
        cudaFuncSetAttribute(proj_mma,  cudaFuncAttributeMaxDynamicSharedMemorySize, GEMM_SMEM_BIG);
        attr_done = true;
    }

    __nv_bfloat16 *xh, *xl, *wqh, *wql, *wph, *wpl;
    cudaGetSymbolAddress((void**)&xh, g_xh);   cudaGetSymbolAddress((void**)&xl, g_xl);
    cudaGetSymbolAddress((void**)&wqh, g_wqh); cudaGetSymbolAddress((void**)&wql, g_wql);
    cudaGetSymbolAddress((void**)&wph, g_wph); cudaGetSymbolAddress((void**)&wpl, g_wpl);

    split_kernel<<<(MTOT * CC / 4 + 255) / 256, 256>>>(x, xh, xl, MTOT * CC);
    split_kernel<<<(3 * CC * CC / 4 + 255) / 256, 256>>>(Wqkv, wqh, wql, 3 * CC * CC);
    split_kernel<<<(CC * CC / 4 + 255) / 256, 256>>>(Wproj, wph, wpl, CC * CC);

    qkv_mma<<<dim3(18, 72), 256, GEMM_SMEM_BIG>>>();
    transpose_v<<<dim3(18, 2, BB * HH), dim3(32, 8)>>>();
    score_mma<<<dim3(5, BB * HH), 256, SCORE_SMEM>>>();
    softmax_mix_kernel<<<MTOT, 384>>>(Wl, bl, Ww, bw);
    av_mma<<<dim3(5, BB * HH), 256, GEMM_SMEM_AV>>>();
    proj_mma<<<dim3(6, 72), 256, GEMM_SMEM_BIG>>>(bproj, out);
}

// round 8
// speedup vs baseline: 2.5938x; 1.0032x over previous
#include <cuda_runtime.h>
#include <cuda_bf16.h>

// Talking-heads attention via mma.sync bf16 tensor cores (plain sm_100 ISA).
// All GEMMs: bf16 hi/lo split (3 MMAs) -> fp32-class accuracy, fp32 accumulators.
// v8: MMA term-reorder — visit all NI accumulators between dependent split-term
//     MMAs (hh/hl/lh) to break the 3-deep RAW chain on each accumulator.

#define BB 16
#define NN 576
#define CC 768
#define HH 12
#define HDIM 64
#define MTOT (BB * NN)
#define SCALE 0.125f
#define ATT ((size_t)BB * HH * NN * NN)
#define QKE (BB * HH * NN * HDIM)

typedef unsigned int u32;

// ============================ PTX helpers (sm_80+ ISA only) ============================
__device__ __forceinline__ u32 smem_u32(const void* p) {
    u32 a;
    asm("{ .reg .u64 t; cvta.to.shared.u64 t, %1; cvt.u32.u64 %0, t; }" : "=r"(a) : "l"(p));
    return a;
}
__device__ __forceinline__ void cp16(u32 dst, const void* src) {
    asm volatile("cp.async.cg.shared.global [%0], [%1], 16;" :: "r"(dst), "l"(src));
}
__device__ __forceinline__ void cp_commit() {
    asm volatile("cp.async.commit_group;" ::: "memory");
}
template <int N>
__device__ __forceinline__ void cp_wait() {
    asm volatile("cp.async.wait_group %0;" :: "n"(N) : "memory");
}
__device__ __forceinline__ void ldm_x4(u32 a, u32& r0, u32& r1, u32& r2, u32& r3) {
    asm volatile("ldmatrix.sync.aligned.m8n8.x4.shared.b16 {%0,%1,%2,%3}, [%4];"
                 : "=r"(r0), "=r"(r1), "=r"(r2), "=r"(r3) : "r"(a));
}
__device__ __forceinline__ void mma_bf16(float* d, const u32* a, const u32* b) {
    asm volatile("mma.sync.aligned.m16n8k16.row.col.f32.bf16.bf16.f32 "
                 "{%0,%1,%2,%3}, {%4,%5,%6,%7}, {%8,%9}, {%0,%1,%2,%3};"
                 : "+f"(d[0]), "+f"(d[1]), "+f"(d[2]), "+f"(d[3])
                 : "r"(a[0]), "r"(a[1]), "r"(a[2]), "r"(a[3]), "r"(b[0]), "r"(b[1]));
}

// ============================ scratch (16B-aligned) ============================
__device__ __align__(16) __nv_bfloat16 g_xh[MTOT * CC], g_xl[MTOT * CC];
__device__ __align__(16) __nv_bfloat16 g_wqh[3 * CC * CC], g_wql[3 * CC * CC];
__device__ __align__(16) __nv_bfloat16 g_wph[CC * CC], g_wpl[CC * CC];
__device__ __align__(16) __nv_bfloat16 g_qh[QKE + 64 * HDIM], g_ql[QKE + 64 * HDIM];
__device__ __align__(16) __nv_bfloat16 g_kh[QKE + 64 * HDIM], g_kl[QKE + 64 * HDIM];
__device__ __align__(16) __nv_bfloat16 g_vh[QKE], g_vl[QKE];
__device__ __align__(16) __nv_bfloat16 g_vth[QKE], g_vtl[QKE];
__device__ __align__(16) float g_attn[ATT];
__device__ __align__(16) __nv_bfloat16 g_a2h[ATT + 64 * NN], g_a2l[ATT + 64 * NN];
__device__ __align__(16) __nv_bfloat16 g_o1h[MTOT * CC], g_o1l[MTOT * CC];

__device__ __forceinline__ u32 pack_hi_lo(float f0, float f1, u32& lo_out) {
    __nv_bfloat16 h0 = __float2bfloat16(f0);
    __nv_bfloat16 h1 = __float2bfloat16(f1);
    __nv_bfloat16 l0 = __float2bfloat16(f0 - __bfloat162float(h0));
    __nv_bfloat16 l1 = __float2bfloat16(f1 - __bfloat162float(h1));
    u32 hw = ((u32)__bfloat16_as_ushort(h1) << 16) | __bfloat16_as_ushort(h0);
    lo_out = ((u32)__bfloat16_as_ushort(l1) << 16) | __bfloat16_as_ushort(l0);
    return hw;
}

// ============================ core GEMM mainloop (3-stage pipeline) ============================
// C[m,n] = sum_k A[m,k]*B[n,k]; BM x BN tile, BK=32, 256 threads, TMW x TNW warps.
// v8: per-acc split terms separated by NI independent MMAs (same per-acc order ->
//     numerics identical to v7).
template <int BM, int BN, int TMW, int TNW>
__device__ __forceinline__ void gemm_core(
    const __nv_bfloat16* __restrict__ Ah, const __nv_bfloat16* __restrict__ Al, int lda,
    const __nv_bfloat16* __restrict__ Bh, const __nv_bfloat16* __restrict__ Bl, int ldb,
    int K, u32 sb, float (*acc)[4][4]) {
    constexpr int MI = BM / TMW / 16;
    constexpr int NI = BN / TNW / 8;
    static_assert(NI == 4, "epilogue layout assumes NI==4");
    constexpr u32 OFF_AL = BM * 64;
    constexpr u32 OFF_BH = 2 * BM * 64;
    constexpr u32 OFF_BL = 2 * BM * 64 + BN * 64;
    constexpr u32 SS = (2 * BM + 2 * BN) * 64;
    const int tid = threadIdx.x;
    const int lane = tid & 31, wid = tid >> 5;
    const int wrow = (wid / TNW) * (BM / TMW);
    const int wcol = (wid % TNW) * (BN / TNW);
    const int NK = K >> 5;

    auto issue = [&](int kt) {
        const u32 st = sb + (u32)(kt % 3) * SS;
        const int k0 = kt << 5;
#pragma unroll
        for (int i = tid; i < BM * 4; i += 256) {
            int r = i >> 2, c = i & 3;
            u32 doff = (u32)(r * 64 + ((c ^ ((r >> 1) & 3)) << 4));
            cp16(st + doff, Ah + (size_t)r * lda + k0 + c * 8);
            cp16(st + OFF_AL + doff, Al + (size_t)r * lda + k0 + c * 8);
        }
#pragma unroll
        for (int i = tid; i < BN * 4; i += 256) {
            int r = i >> 2, c = i & 3;
            u32 doff = (u32)(r * 64 + ((c ^ ((r >> 1) & 3)) << 4));
            cp16(st + OFF_BH + doff, Bh + (size_t)r * ldb + k0 + c * 8);
            cp16(st + OFF_BL + doff, Bl + (size_t)r * ldb + k0 + c * 8);
        }
        cp_commit();
    };

    issue(0);
    if (NK > 1) issue(1);
    for (int kt = 0; kt < NK; kt++) {
        if (kt + 1 < NK) cp_wait<1>();
        else             cp_wait<0>();
        __syncthreads();
        if (kt + 2 < NK) issue(kt + 2);
        const u32 st = sb + (u32)(kt % 3) * SS;
#pragma unroll
        for (int ks = 0; ks < 2; ks++) {
            u32 bhf[NI][2], blf[NI][2];
            {
                const int kc = ks * 2 + ((lane >> 3) & 1);
                const int rb = wcol + ((lane >> 4) << 3) + (lane & 7);
#pragma unroll
                for (int ni = 0; ni < NI; ni += 2) {
                    int r = rb + ni * 8;
                    u32 swz = (u32)(r * 64 + ((kc ^ ((r >> 1) & 3)) << 4));
                    ldm_x4(st + OFF_BH + swz, bhf[ni][0], bhf[ni][1], bhf[ni + 1][0], bhf[ni + 1][1]);
                    ldm_x4(st + OFF_BL + swz, blf[ni][0], blf[ni][1], blf[ni + 1][0], blf[ni + 1][1]);
                }
            }
            const int kcA = ks * 2 + (lane >> 4);
#pragma unroll
            for (int mi = 0; mi < MI; mi++) {
                int r = wrow + mi * 16 + (lane & 15);
                u32 a = st + (u32)(r * 64 + ((kcA ^ ((r >> 1) & 3)) << 4));
                u32 ahf[4], alf[4];
                ldm_x4(a, ahf[0], ahf[1], ahf[2], ahf[3]);
                ldm_x4(a + OFF_AL, alf[0], alf[1], alf[2], alf[3]);
                // term-major order: all NI accs between dependent MMAs on one acc
#pragma unroll
                for (int ni = 0; ni < NI; ni++) mma_bf16(acc[mi][ni], ahf, bhf[ni]);  // hi*hi
#pragma unroll
                for (int ni = 0; ni < NI; ni++) mma_bf16(acc[mi][ni], ahf, blf[ni]);  // hi*lo
#pragma unroll
                for (int ni = 0; ni < NI; ni++) mma_bf16(acc[mi][ni], alf, bhf[ni]);  // lo*hi
            }
        }
    }
}

#define GEMM_SMEM_BIG 98304   // 3 stages x 32768 (BM=128,BN=128)
#define GEMM_SMEM_AV  73728   // 3 stages x 24576 (BM=128,BN=64)
#define SCORE_SMEM    81920   // A 32768 + 3 stages x 16384

// ============================ fp32 -> bf16 hi/lo split ============================
__global__ __launch_bounds__(256) void split_kernel(const float* __restrict__ in,
                                                    __nv_bfloat16* __restrict__ hi,
                                                    __nv_bfloat16* __restrict__ lo, int n) {
    int i = (blockIdx.x * 256 + threadIdx.x) * 4;
    if (i >= n) return;
    float4 v = *reinterpret_cast<const float4*>(in + i);
    u32 l0, l1;
    u32 h0 = pack_hi_lo(v.x, v.y, l0);
    u32 h1 = pack_hi_lo(v.z, v.w, l1);
    *reinterpret_cast<uint2*>(hi + i) = make_uint2(h0, h1);
    *reinterpret_cast<uint2*>(lo + i) = make_uint2(l0, l1);
}

// ============================ QKV GEMM + scatter (BN=128) ============================
// grid (2304/128=18, 9216/128=72)
__global__ __launch_bounds__(256, 2) void qkv_mma() {
    extern __shared__ char smem[];
    u32 sb = smem_u32(smem);
    const int n0 = blockIdx.x * 128, m0 = blockIdx.y * 128;
    float acc[4][4][4];
#pragma unroll
    for (int i = 0; i < 4; i++)
#pragma unroll
        for (int j = 0; j < 4; j++)
#pragma unroll
            for (int k = 0; k < 4; k++) acc[i][j][k] = 0.f;
    gemm_core<128, 128, 2, 4>(g_xh + (size_t)m0 * CC, g_xl + (size_t)m0 * CC, CC,
                              g_wqh + (size_t)n0 * CC, g_wql + (size_t)n0 * CC, CC,
                              CC, sb, acc);
    const int tid = threadIdx.x, lane = tid & 31, wid = tid >> 5;
    const int wm = wid >> 2, wn = wid & 3;
#pragma unroll
    for (int mi = 0; mi < 4; mi++)
#pragma unroll
        for (int ni = 0; ni < 4; ni++) {
            int c = n0 + wn * 32 + ni * 8 + (lane & 3) * 2;
            int t = c / CC, rc = c - t * CC, h = rc >> 6, d0 = rc & 63;
            float sc = (t == 0) ? SCALE : 1.f;
            __nv_bfloat16* ph = (t == 0) ? g_qh : (t == 1) ? g_kh : g_vh;
            __nv_bfloat16* pl = (t == 0) ? g_ql : (t == 1) ? g_kl : g_vl;
#pragma unroll
            for (int hf = 0; hf < 2; hf++) {
                int m = m0 + wm * 64 + mi * 16 + (lane >> 2) + hf * 8;
                int b = m / NN, ntok = m - b * NN;
                size_t base = ((size_t)(b * HH + h) * NN + ntok) * HDIM + d0;
                u32 lw, hw = pack_hi_lo(acc[mi][ni][hf * 2] * sc, acc[mi][ni][hf * 2 + 1] * sc, lw);
                *reinterpret_cast<u32*>(ph + base) = hw;
                *reinterpret_cast<u32*>(pl + base) = lw;
            }
        }
}

// ============================ transpose V -> vT[d][n] ============================
__global__ __launch_bounds__(256) void transpose_v() {
    __shared__ __nv_bfloat16 th[32][33], tl[32][33];
    int n0 = blockIdx.x * 32, d0 = blockIdx.y * 32, bh = blockIdx.z;
    int tx = threadIdx.x, ty = threadIdx.y;
#pragma unroll
    for (int i = 0; i < 4; i++) {
        int n = n0 + ty + i * 8;
        size_t s = ((size_t)bh * NN + n) * HDIM + d0 + tx;
        th[ty + i * 8][tx] = g_vh[s];
        tl[ty + i * 8][tx] = g_vl[s];
    }
    __syncthreads();
#pragma unroll
    for (int i = 0; i < 4; i++) {
        int d = d0 + ty + i * 8;
        size_t t = ((size_t)bh * HDIM + d) * NN + n0 + tx;
        g_vth[t] = th[tx][ty + i * 8];
        g_vtl[t] = tl[tx][ty + i * 8];
    }
}

// ============================ score: persistent-Q n-loop kernel ============================
// grid (5, 192). Q tile resident; K tiles stream through a 3-stage ring.
__global__ __launch_bounds__(256) void score_mma() {
    extern __shared__ char smem[];
    u32 sb = smem_u32(smem);
    const u32 A_HI = 0, A_LO = 16384, RING = 32768;
    const int m0 = blockIdx.x * 128, bhi = blockIdx.y;
    const int tid = threadIdx.x, lane = tid & 31, wid = tid >> 5;
    const int wm = wid >> 1, wn = wid & 1;
    const int wrow = wm * 32, wcol = wn * 32;

    const __nv_bfloat16* Qh = g_qh + ((size_t)bhi * NN + m0) * HDIM;
    const __nv_bfloat16* Ql = g_ql + ((size_t)bhi * NN + m0) * HDIM;
    const __nv_bfloat16* Kh = g_kh + (size_t)bhi * NN * HDIM;
    const __nv_bfloat16* Kl = g_kl + (size_t)bhi * NN * HDIM;

#pragma unroll
    for (int i = tid; i < 128 * 8; i += 256) {
        int r = i >> 3, cc = i & 7, kt = cc >> 2, c = cc & 3;
        u32 doff = (u32)(kt * 8192 + r * 64 + ((c ^ ((r >> 1) & 3)) << 4));
        size_t so = (size_t)r * HDIM + kt * 32 + c * 8;
        cp16(sb + A_HI + doff, Qh + so);
        cp16(sb + A_LO + doff, Ql + so);
    }
    cp_commit();

    auto issueB = [&](int nt) {
        const u32 st = sb + RING + (u32)(nt % 3) * 16384;
#pragma unroll
        for (int i = tid; i < 64 * 8; i += 256) {
            int r = i >> 3, cc = i & 7, kt = cc >> 2, c = cc & 3;
            u32 doff = (u32)(kt * 4096 + r * 64 + ((c ^ ((r >> 1) & 3)) << 4));
            size_t so = (size_t)(nt * 64 + r) * HDIM + kt * 32 + c * 8;
            cp16(st + doff, Kh + so);
            cp16(st + 8192 + doff, Kl + so);
        }
        cp_commit();
    };
    issueB(0); issueB(1);

    float* outb = g_attn + (size_t)bhi * NN * NN;
    for (int nt = 0; nt < 9; nt++) {
        if (nt < 8) cp_wait<1>();
        else        cp_wait<0>();
        __syncthreads();
        if (nt + 2 < 9) issueB(nt + 2);
        const u32 st = sb + RING + (u32)(nt % 3) * 16384;

        float acc[2][4][4];
#pragma unroll
        for (int i = 0; i < 2; i++)
#pragma unroll
            for (int j = 0; j < 4; j++)
#pragma unroll
                for (int k = 0; k < 4; k++) acc[i][j][k] = 0.f;

#pragma unroll
        for (int kt = 0; kt < 2; kt++)
#pragma unroll
            for (int ks = 0; ks < 2; ks++) {
                u32 bhf[4][2], blf[4][2];
                {
                    const int kc = ks * 2 + ((lane >> 3) & 1);
                    const int rb = wcol + ((lane >> 4) << 3) + (lane & 7);
#pragma unroll
                    for (int ni = 0; ni < 4; ni += 2) {
                        int r = rb + ni * 8;
                        u32 swz = (u32)(kt * 4096 + r * 64 + ((kc ^ ((r >> 1) & 3)) << 4));
                        ldm_x4(st + swz, bhf[ni][0], bhf[ni][1], bhf[ni + 1][0], bhf[ni + 1][1]);
                        ldm_x4(st + 8192 + swz, blf[ni][0], blf[ni][1], blf[ni + 1][0], blf[ni + 1][1]);
                    }
                }
                const int kcA = ks * 2 + (lane >> 4);
#pragma unroll
                for (int mi = 0; mi < 2; mi++) {
                    int r = wrow + mi * 16 + (lane & 15);
                    u32 aoff = (u32)(kt * 8192 + r * 64 + ((kcA ^ ((r >> 1) & 3)) << 4));
                    u32 ahf[4], alf[4];
                    ldm_x4(sb + A_HI + aoff, ahf[0], ahf[1], ahf[2], ahf[3]);
                    ldm_x4(sb + A_LO + aoff, alf[0], alf[1], alf[2], alf[3]);
#pragma unroll
                    for (int ni = 0; ni < 4; ni++) mma_bf16(acc[mi][ni], ahf, bhf[ni]);
#pragma unroll
                    for (int ni = 0; ni < 4; ni++) mma_bf16(acc[mi][ni], ahf, blf[ni]);
#pragma unroll
                    for (int ni = 0; ni < 4; ni++) mma_bf16(acc[mi][ni], alf, bhf[ni]);
                }
            }

        const int n0 = nt * 64;
#pragma unroll
        for (int mi = 0; mi < 2; mi++)
#pragma unroll
            for (int ni = 0; ni < 4; ni++) {
                int c = n0 + wn * 32 + ni * 8 + (lane & 3) * 2;
#pragma unroll
                for (int hf = 0; hf < 2; hf++) {
                    int m = m0 + wm * 32 + mi * 16 + (lane >> 2) + hf * 8;
                    if (m < NN)
                        *reinterpret_cast<float2*>(outb + (size_t)m * NN + c) =
                            make_float2(acc[mi][ni][hf * 2], acc[mi][ni][hf * 2 + 1]);
                }
            }
    }
}

// ============================ softmax + both talking-heads mixes ============================
__global__ __launch_bounds__(384) void softmax_mix_kernel(const float* __restrict__ Wl,
                                                          const float* __restrict__ bl,
                                                          const float* __restrict__ Ww,
                                                          const float* __restrict__ bw) {
    __shared__ __align__(16) float sm[HH][NN];
    __shared__ float wls[HH * HH], bls[HH], wws[HH * HH], bws[HH];
    const int bm = blockIdx.x;
    const int b = bm / NN, m = bm % NN;
    const int tid = threadIdx.x, lane = tid & 31, wid = tid >> 5;

    if (tid < HH * HH) { wls[tid] = Wl[tid]; wws[tid] = Ww[tid]; }
    if (tid < HH) { bls[tid] = bl[tid]; bws[tid] = bw[tid]; }

    for (int idx = tid; idx < HH * NN / 4; idx += 384) {
        int h = idx / (NN / 4), n4 = idx - h * (NN / 4);
        float4 v = *reinterpret_cast<const float4*>(
            &g_attn[((size_t)(b * HH + h) * NN + m) * NN + n4 * 4]);
        *reinterpret_cast<float4*>(&sm[h][n4 * 4]) = v;
    }
    __syncthreads();

    for (int n = tid; n < NN; n += 384) {
        float p[HH];
#pragma unroll
        for (int h = 0; h < HH; h++) p[h] = sm[h][n];
#pragma unroll
        for (int g = 0; g < HH; g++) {
            float o = bls[g];
#pragma unroll
            for (int h = 0; h < HH; h++) o += wls[g * HH + h] * p[h];
            sm[g][n] = o;
        }
    }
    __syncthreads();

    {
        const int h = wid;
        float mx = -1e30f;
        for (int n = lane; n < NN; n += 32) mx = fmaxf(mx, sm[h][n]);
#pragma unroll
        for (int o = 16; o > 0; o >>= 1) mx = fmaxf(mx, __shfl_xor_sync(0xffffffffu, mx, o));
        float sum = 0.f;
        for (int n = lane; n < NN; n += 32) {
            float e = __expf(sm[h][n] - mx);
            sm[h][n] = e; sum += e;
        }
#pragma unroll
        for (int o = 16; o > 0; o >>= 1) sum += __shfl_xor_sync(0xffffffffu, sum, o);
        float inv = 1.f / sum;
        for (int n = lane; n < NN; n += 32) sm[h][n] *= inv;
    }
    __syncthreads();

    for (int n2 = tid; n2 < NN / 2; n2 += 384) {
        int n = n2 * 2;
        float p0[HH], p1[HH];
#pragma unroll
        for (int h = 0; h < HH; h++) { p0[h] = sm[h][n]; p1[h] = sm[h][n + 1]; }
#pragma unroll
        for (int g = 0; g < HH; g++) {
            float o0 = bws[g], o1 = bws[g];
#pragma unroll
            for (int h = 0; h < HH; h++) { o0 += wws[g * HH + h] * p0[h]; o1 += wws[g * HH + h] * p1[h]; }
            size_t idx = ((size_t)(b * HH + g) * NN + m) * NN + n;
            u32 lw, hw = pack_hi_lo(o0, o1, lw);
            *reinterpret_cast<u32*>(g_a2h + idx) = hw;
            *reinterpret_cast<u32*>(g_a2l + idx) = lw;
        }
    }
}

// ============================ O = attn2 @ V per (b,h) ============================
// grid (5, 192). K = 576.
__global__ __launch_bounds__(256) void av_mma() {
    extern __shared__ char smem[];
    u32 sb = smem_u32(smem);
    const int m0 = blockIdx.x * 128, bh = blockIdx.y;
    float acc[2][4][4];
#pragma unroll
    for (int i = 0; i < 2; i++)
#pragma unroll
        for (int j = 0; j < 4; j++)
#pragma unroll
            for (int k = 0; k < 4; k++) acc[i][j][k] = 0.f;
    const size_t ab = (size_t)bh * NN * NN + (size_t)m0 * NN;
    const size_t bb = (size_t)bh * HDIM * NN;
    gemm_core<128, 64, 4, 2>(g_a2h + ab, g_a2l + ab, NN,
                             g_vth + bb, g_vtl + bb, NN, NN, sb, acc);
    const int tid = threadIdx.x, lane = tid & 31, wid = tid >> 5;
    const int wm = wid >> 1, wn = wid & 1;
    const int b = bh / HH, h = bh - b * HH;
#pragma unroll
    for (int mi = 0; mi < 2; mi++)
#pragma unroll
        for (int ni = 0; ni < 4; ni++) {
            int dc = wn * 32 + ni * 8 + (lane & 3) * 2;
#pragma unroll
            for (int hf = 0; hf < 2; hf++) {
                int m = m0 + wm * 32 + mi * 16 + (lane >> 2) + hf * 8;
                if (m < NN) {
                    size_t base = ((size_t)b * NN + m) * CC + h * HDIM + dc;
                    u32 lw, hw = pack_hi_lo(acc[mi][ni][hf * 2], acc[mi][ni][hf * 2 + 1], lw);
                    *reinterpret_cast<u32*>(g_o1h + base) = hw;
                    *reinterpret_cast<u32*>(g_o1l + base) = lw;
                }
            }
        }
}

// ============================ out = o1 @ Wproj^T + bias (BN=128) ============================
// grid (6, 72)
__global__ __launch_bounds__(256, 2) void proj_mma(const float* __restrict__ bias,
                                                   float* __restrict__ out) {
    extern __shared__ char smem[];
    u32 sb = smem_u32(smem);
    const int n0 = blockIdx.x * 128, m0 = blockIdx.y * 128;
    float acc[4][4][4];
#pragma unroll
    for (int i = 0; i < 4; i++)
#pragma unroll
        for (int j = 0; j < 4; j++)
#pragma unroll
            for (int k = 0; k < 4; k++) acc[i][j][k] = 0.f;
    gemm_core<128, 128, 2, 4>(g_o1h + (size_t)m0 * CC, g_o1l + (size_t)m0 * CC, CC,
                              g_wph + (size_t)n0 * CC, g_wpl + (size_t)n0 * CC, CC,
                              CC, sb, acc);
    const int tid = threadIdx.x, lane = tid & 31, wid = tid >> 5;
    const int wm = wid >> 2, wn = wid & 3;
#pragma unroll
    for (int mi = 0; mi < 4; mi++)
#pragma unroll
        for (int ni = 0; ni < 4; ni++) {
            int c = n0 + wn * 32 + ni * 8 + (lane & 3) * 2;
            float b0 = __ldg(&bias[c]), b1 = __ldg(&bias[c + 1]);
#pragma unroll
            for (int hf = 0; hf < 2; hf++) {
                int m = m0 + wm * 64 + mi * 16 + (lane >> 2) + hf * 8;
                *reinterpret_cast<float2*>(out + (size_t)m * CC + c) =
                    make_float2(acc[mi][ni][hf * 2] + b0, acc[mi][ni][hf * 2 + 1] + b1);
            }
        }
}

// ============================ launch ============================
extern "C" void kernel_launch(void* const* d_in, const int* in_sizes, int n_in,
                              void* d_out, int out_size) {
    const float* x     = (const float*)d_in[0];
    const float* Wqkv  = (const float*)d_in[1];
    const float* Wl    = (const float*)d_in[2];
    const float* bl    = (const float*)d_in[3];
    const float* Ww    = (const float*)d_in[4];
    const float* bw    = (const float*)d_in[5];
    const float* Wproj = (const float*)d_in[6];
    const float* bproj = (const float*)d_in[7];
    float* out = (float*)d_out;

    static bool attr_done = false;
    if (!attr_done) {
        cudaFuncSetAttribute(qkv_mma,   cudaFuncAttributeMaxDynamicSharedMemorySize, GEMM_SMEM_BIG);
        cudaFuncSetAttribute(score_mma, cudaFuncAttributeMaxDynamicSharedMemorySize, SCORE_SMEM);
        cudaFuncSetAttribute(av_mma,    cudaFuncAttributeMaxDynamicSharedMemorySize, GEMM_SMEM_AV);
        cudaFuncSetAttribute(proj_mma,  cudaFuncAttributeMaxDynamicSharedMemorySize, GEMM_SMEM_BIG);
        attr_done = true;
    }

    __nv_bfloat16 *xh, *xl, *wqh, *wql, *wph, *wpl;
    cudaGetSymbolAddress((void**)&xh, g_xh);   cudaGetSymbolAddress((void**)&xl, g_xl);
    cudaGetSymbolAddress((void**)&wqh, g_wqh); cudaGetSymbolAddress((void**)&wql, g_wql);
    cudaGetSymbolAddress((void**)&wph, g_wph); cudaGetSymbolAddress((void**)&wpl, g_wpl);

    split_kernel<<<(MTOT * CC / 4 + 255) / 256, 256>>>(x, xh, xl, MTOT * CC);
    split_kernel<<<(3 * CC * CC / 4 + 255) / 256, 256>>>(Wqkv, wqh, wql, 3 * CC * CC);
    split_kernel<<<(CC * CC / 4 + 255) / 256, 256>>>(Wproj, wph, wpl, CC * CC);

    qkv_mma<<<dim3(18, 72), 256, GEMM_SMEM_BIG>>>();
    transpose_v<<<dim3(18, 2, BB * HH), dim3(32, 8)>>>();
    score_mma<<<dim3(5, BB * HH), 256, SCORE_SMEM>>>();
    softmax_mix_kernel<<<MTOT, 384>>>(Wl, bl, Ww, bw);
    av_mma<<<dim3(5, BB * HH), 256, GEMM_SMEM_AV>>>();
    proj_mma<<<dim3(6, 72), 256, GEMM_SMEM_BIG>>>(bproj, out);
}